// round 1
// baseline (speedup 1.0000x reference)
#include <cuda_runtime.h>
#include <cuda_bf16.h>
#include <math.h>

#define N_ROWS 65536
#define D_IN   256
#define F1     512
#define F2     2048
#define EPS    1e-5f

// ---------------- scratch (static device globals; no allocations) ----------
__device__ float g_xn[(size_t)N_ROWS * D_IN];     //  64 MB
__device__ float g_h1[(size_t)N_ROWS * F1];       // 128 MB
__device__ float g_h2[(size_t)N_ROWS * F2];       // 512 MB
__device__ float g_sum[D_IN];
__device__ float g_sumsq[D_IN];
__device__ float g_scale[D_IN];
__device__ float g_shift[D_IN];

// ---------------- BN stage -------------------------------------------------
__global__ void bn_zero() {
    g_sum[threadIdx.x]   = 0.f;
    g_sumsq[threadIdx.x] = 0.f;
}

// 256 blocks x 256 threads; each block handles 256 rows, thread j owns column j.
__global__ void bn_reduce(const float* __restrict__ x) {
    const int col = threadIdx.x;
    const int rows_per_block = N_ROWS / gridDim.x;
    size_t base = (size_t)blockIdx.x * rows_per_block * D_IN + col;
    float s = 0.f, sq = 0.f;
    #pragma unroll 8
    for (int r = 0; r < rows_per_block; ++r) {
        float v = x[base + (size_t)r * D_IN];
        s += v; sq += v * v;
    }
    atomicAdd(&g_sum[col], s);
    atomicAdd(&g_sumsq[col], sq);
}

__global__ void bn_finalize(const float* __restrict__ gamma,
                            const float* __restrict__ beta) {
    int j = threadIdx.x;
    float inv_n = 1.0f / (float)N_ROWS;
    float mu  = g_sum[j] * inv_n;
    float var = g_sumsq[j] * inv_n - mu * mu;
    float sc  = gamma[j] * rsqrtf(var + EPS);
    g_scale[j] = sc;
    g_shift[j] = beta[j] - mu * sc;
}

// normalize, write xn to scratch and tanh(xn) to raw_feats output. float4 vectorized.
__global__ void bn_apply(const float* __restrict__ x,
                         float* __restrict__ xn_out,
                         float* __restrict__ raw_out) {
    size_t i4 = (size_t)blockIdx.x * blockDim.x + threadIdx.x;   // float4 index
    size_t i  = i4 * 4;
    int c = (int)(i & (D_IN - 1));
    float4 xv = *(const float4*)(x + i);
    float4 sc = *(const float4*)(g_scale + c);
    float4 sh = *(const float4*)(g_shift + c);
    float4 xn;
    xn.x = fmaf(xv.x, sc.x, sh.x);
    xn.y = fmaf(xv.y, sc.y, sh.y);
    xn.z = fmaf(xv.z, sc.z, sh.z);
    xn.w = fmaf(xv.w, sc.w, sh.w);
    *(float4*)(xn_out + i) = xn;
    float4 t;
    t.x = tanhf(xn.x); t.y = tanhf(xn.y); t.z = tanhf(xn.z); t.w = tanhf(xn.w);
    *(float4*)(raw_out + i) = t;
}

// ---------------- GEMM_NT: C[N,F] = A[N,K] @ W[F,K]^T + bias, opt tanh ------
// BM=BN=128, BK=8, 256 threads, 8x8 register tile per thread.
template<bool TANH>
__global__ __launch_bounds__(256, 2)
void gemm_nt(const float* __restrict__ A, const float* __restrict__ W,
             const float* __restrict__ bias, float* __restrict__ C,
             int K, int F) {
    __shared__ float As[8][132];
    __shared__ float Bs[8][132];

    const int tid = threadIdx.x;
    const int tx = tid & 15;          // 0..15 -> N dim
    const int ty = tid >> 4;          // 0..15 -> M dim
    const int bm = blockIdx.y * 128;
    const int bn = blockIdx.x * 128;

    // loader mapping: 2 threads per row, float4 each (8 k-values per row)
    const int lrow = tid >> 1;        // 0..127
    const int lk   = (tid & 1) * 4;   // 0 or 4

    const float* Aptr = A + (size_t)(bm + lrow) * K + lk;
    const float* Wptr = W + (size_t)(bn + lrow) * K + lk;

    float acc[8][8];
    #pragma unroll
    for (int i = 0; i < 8; ++i)
        #pragma unroll
        for (int j = 0; j < 8; ++j) acc[i][j] = 0.f;

    for (int k0 = 0; k0 < K; k0 += 8) {
        float4 a = *(const float4*)(Aptr + k0);
        float4 b = *(const float4*)(Wptr + k0);
        As[lk + 0][lrow] = a.x; As[lk + 1][lrow] = a.y;
        As[lk + 2][lrow] = a.z; As[lk + 3][lrow] = a.w;
        Bs[lk + 0][lrow] = b.x; Bs[lk + 1][lrow] = b.y;
        Bs[lk + 2][lrow] = b.z; Bs[lk + 3][lrow] = b.w;
        __syncthreads();

        #pragma unroll
        for (int k = 0; k < 8; ++k) {
            float4 ra0 = *(const float4*)&As[k][ty * 8];
            float4 ra1 = *(const float4*)&As[k][ty * 8 + 4];
            float4 rb0 = *(const float4*)&Bs[k][tx * 8];
            float4 rb1 = *(const float4*)&Bs[k][tx * 8 + 4];
            float ra[8] = {ra0.x, ra0.y, ra0.z, ra0.w, ra1.x, ra1.y, ra1.z, ra1.w};
            float rb[8] = {rb0.x, rb0.y, rb0.z, rb0.w, rb1.x, rb1.y, rb1.z, rb1.w};
            #pragma unroll
            for (int i = 0; i < 8; ++i)
                #pragma unroll
                for (int j = 0; j < 8; ++j)
                    acc[i][j] = fmaf(ra[i], rb[j], acc[i][j]);
        }
        __syncthreads();
    }

    // epilogue
    float bj[8];
    #pragma unroll
    for (int j = 0; j < 8; ++j) bj[j] = bias[bn + tx * 8 + j];

    #pragma unroll
    for (int i = 0; i < 8; ++i) {
        int row = bm + ty * 8 + i;
        float* Crow = C + (size_t)row * F + bn + tx * 8;
        float4 v0, v1;
        float v[8];
        #pragma unroll
        for (int j = 0; j < 8; ++j) {
            float t = acc[i][j] + bj[j];
            v[j] = TANH ? tanhf(t) : t;
        }
        v0.x = v[0]; v0.y = v[1]; v0.z = v[2]; v0.w = v[3];
        v1.x = v[4]; v1.y = v[5]; v1.z = v[6]; v1.w = v[7];
        *(float4*)(Crow)     = v0;
        *(float4*)(Crow + 4) = v1;
    }
}

// ---------------- launch ---------------------------------------------------
extern "C" void kernel_launch(void* const* d_in, const int* in_sizes, int n_in,
                              void* d_out, int out_size) {
    const float* x     = (const float*)d_in[0];
    const float* gamma = (const float*)d_in[1];
    const float* beta  = (const float*)d_in[2];
    const float* W1    = (const float*)d_in[3];
    const float* b1    = (const float*)d_in[4];
    const float* W2    = (const float*)d_in[5];
    const float* b2    = (const float*)d_in[6];
    const float* Wf    = (const float*)d_in[7];
    const float* bf    = (const float*)d_in[8];

    float* out_main = (float*)d_out;                              // [N, 256]
    float* out_raw  = (float*)d_out + (size_t)N_ROWS * D_IN;      // [N, 256]

    float *xn, *h1, *h2;
    cudaGetSymbolAddress((void**)&xn, g_xn);
    cudaGetSymbolAddress((void**)&h1, g_h1);
    cudaGetSymbolAddress((void**)&h2, g_h2);

    // BatchNorm statistics
    bn_zero<<<1, 256>>>();
    bn_reduce<<<256, 256>>>(x);
    bn_finalize<<<1, 256>>>(gamma, beta);

    // normalize + raw_feats
    {
        size_t n4 = (size_t)N_ROWS * D_IN / 4;
        bn_apply<<<(unsigned)(n4 / 256), 256>>>(x, xn, out_raw);
    }

    // MLP
    gemm_nt<false><<<dim3(F1 / 128,  N_ROWS / 128), 256>>>(xn, W1, b1, h1, D_IN, F1);
    gemm_nt<false><<<dim3(F2 / 128,  N_ROWS / 128), 256>>>(h1, W2, b2, h2, F1, F2);
    gemm_nt<true ><<<dim3(D_IN / 128, N_ROWS / 128), 256>>>(h2, Wf, bf, out_main, F2, D_IN);
}

// round 2
// speedup vs baseline: 7.8455x; 7.8455x over previous
#include <cuda_runtime.h>
#include <cuda_bf16.h>
#include <math.h>

#define N_ROWS 65536
#define D_IN   256
#define F1     512
#define F2     2048
#define EPS    1e-5f

// ---------------- scratch (static device globals; no allocations) ----------
__device__ float g_sum[D_IN];
__device__ float g_sumsq[D_IN];
__device__ float g_scale[D_IN];
__device__ float g_shift[D_IN];

__device__ float g_part0[8 * 256 * 512];   // split-K partials for T0 = Wf@W2
__device__ float g_T0[256 * 512];          // Wf@W2
__device__ float g_part1[4 * 256 * 256];   // split-K partials for Weff
__device__ float g_Weff[256 * 256];        // Wf@W2@W1
__device__ float g_Wx[256 * 256];          // Weff * scale[k]
__device__ float g_v1[F2];                 // W2@b1 + b2
__device__ float g_v2[D_IN];               // Wf@v1 + bf
__device__ float g_beff[D_IN];             // v2 + Weff@shift

// ---------------- BN stats -------------------------------------------------
__global__ void bn_zero() {
    g_sum[threadIdx.x]   = 0.f;
    g_sumsq[threadIdx.x] = 0.f;
}

__global__ void bn_reduce(const float* __restrict__ x) {
    const int col = threadIdx.x;
    const int rows_per_block = N_ROWS / gridDim.x;
    size_t base = (size_t)blockIdx.x * rows_per_block * D_IN + col;
    float s = 0.f, sq = 0.f;
    #pragma unroll 8
    for (int r = 0; r < rows_per_block; ++r) {
        float v = x[base + (size_t)r * D_IN];
        s += v; sq += v * v;
    }
    atomicAdd(&g_sum[col], s);
    atomicAdd(&g_sumsq[col], sq);
}

__global__ void bn_finalize(const float* __restrict__ gamma,
                            const float* __restrict__ beta) {
    int j = threadIdx.x;
    float inv_n = 1.0f / (float)N_ROWS;
    float mu  = g_sum[j] * inv_n;
    float var = g_sumsq[j] * inv_n - mu * mu;
    float sc  = gamma[j] * rsqrtf(var + EPS);
    g_scale[j] = sc;
    g_shift[j] = beta[j] - mu * sc;
}

// raw_feats = tanh(x * scale + shift), float4 vectorized
__global__ void bn_raw(const float* __restrict__ x, float* __restrict__ raw_out) {
    size_t i4 = (size_t)blockIdx.x * blockDim.x + threadIdx.x;
    size_t i  = i4 * 4;
    int c = (int)(i & (D_IN - 1));
    float4 xv = *(const float4*)(x + i);
    float4 sc = *(const float4*)(g_scale + c);
    float4 sh = *(const float4*)(g_shift + c);
    float4 t;
    t.x = tanhf(fmaf(xv.x, sc.x, sh.x));
    t.y = tanhf(fmaf(xv.y, sc.y, sh.y));
    t.z = tanhf(fmaf(xv.z, sc.z, sh.z));
    t.w = tanhf(fmaf(xv.w, sc.w, sh.w));
    *(float4*)(raw_out + i) = t;
}

// ---------------- small NN GEMM with deterministic split-K ------------------
// P[s, M, N] partial = A[M,K_chunk_s] @ B[K_chunk_s, N]; both row-major.
// grid: (N/64, M/64, S). block 256. BM=BN=64, BK=16, 4x4 per thread.
__global__ void gemm_nn_split(const float* __restrict__ A,
                              const float* __restrict__ B,
                              float* __restrict__ P,
                              int M, int N, int K, int kchunk) {
    __shared__ float As[16][64];
    __shared__ float Bs[16][65];

    const int tid = threadIdx.x;
    const int tx = tid & 15;        // N dir
    const int ty = tid >> 4;        // M dir
    const int bn = blockIdx.x * 64;
    const int bm = blockIdx.y * 64;
    const int k0 = blockIdx.z * kchunk;

    float acc[4][4];
    #pragma unroll
    for (int i = 0; i < 4; ++i)
        #pragma unroll
        for (int j = 0; j < 4; ++j) acc[i][j] = 0.f;

    for (int kb = k0; kb < k0 + kchunk; kb += 16) {
        // load A tile 64x16 (1024 elems, 4 per thread)
        #pragma unroll
        for (int t = 0; t < 4; ++t) {
            int idx = tid * 4 + t;          // kk fastest
            int r  = idx >> 4;
            int kk = idx & 15;
            As[kk][r] = A[(size_t)(bm + r) * K + kb + kk];
        }
        // load B tile 16x64 (1024 elems)
        #pragma unroll
        for (int t = 0; t < 4; ++t) {
            int idx = tid + t * 256;
            int c  = idx & 63;
            int kk = idx >> 6;
            Bs[kk][c] = B[(size_t)(kb + kk) * N + bn + c];
        }
        __syncthreads();

        #pragma unroll
        for (int kk = 0; kk < 16; ++kk) {
            float a[4], b[4];
            #pragma unroll
            for (int i = 0; i < 4; ++i) a[i] = As[kk][ty * 4 + i];
            #pragma unroll
            for (int j = 0; j < 4; ++j) b[j] = Bs[kk][tx * 4 + j];
            #pragma unroll
            for (int i = 0; i < 4; ++i)
                #pragma unroll
                for (int j = 0; j < 4; ++j)
                    acc[i][j] = fmaf(a[i], b[j], acc[i][j]);
        }
        __syncthreads();
    }

    float* Pb = P + (size_t)blockIdx.z * M * N;
    #pragma unroll
    for (int i = 0; i < 4; ++i)
        #pragma unroll
        for (int j = 0; j < 4; ++j)
            Pb[(size_t)(bm + ty * 4 + i) * N + bn + tx * 4 + j] = acc[i][j];
}

// C[i] = sum_s P[s*MN + i]  (deterministic reduction)
__global__ void reduce_splits(const float* __restrict__ P, float* __restrict__ C,
                              int MN, int S) {
    int i = blockIdx.x * 256 + threadIdx.x;
    if (i >= MN) return;
    float s = 0.f;
    for (int k = 0; k < S; ++k) s += P[(size_t)k * MN + i];
    C[i] = s;
}

// v1[i] = dot(W2 row i, b1) + b2[i]
__global__ void bias_chain1(const float* __restrict__ W2, const float* __restrict__ b1,
                            const float* __restrict__ b2) {
    int i = blockIdx.x * 256 + threadIdx.x;
    if (i >= F2) return;
    float s = 0.f;
    const float* row = W2 + (size_t)i * F1;
    for (int k = 0; k < F1; ++k) s = fmaf(row[k], b1[k], s);
    g_v1[i] = s + b2[i];
}

// v2[i] = dot(Wf row i, v1) + bf[i]
__global__ void bias_chain2(const float* __restrict__ Wf, const float* __restrict__ bf) {
    int i = threadIdx.x;
    float s = 0.f;
    const float* row = Wf + (size_t)i * F2;
    for (int k = 0; k < F2; ++k) s = fmaf(row[k], g_v1[k], s);
    g_v2[i] = s + bf[i];
}

// Wx[i,k] = Weff[i,k]*scale[k];  beff[i] = v2[i] + dot(Weff row i, shift)
__global__ void fold_bn() {
    int i = blockIdx.x;     // 256 rows
    int t = threadIdx.x;    // 256 cols
    float w = g_Weff[i * D_IN + t];
    g_Wx[i * D_IN + t] = w * g_scale[t];
    // row-dot via shared reduction
    __shared__ float red[256];
    red[t] = w * g_shift[t];
    __syncthreads();
    for (int off = 128; off > 0; off >>= 1) {
        if (t < off) red[t] += red[t + off];
        __syncthreads();
    }
    if (t == 0) g_beff[i] = g_v2[i] + red[0];
}

// ---------------- big GEMM_NT: C[N,F] = A[N,K] @ W[F,K]^T + bias, tanh ------
// BM=BN=128, BK=8, 256 threads, 8x8 register tile per thread.
template<bool TANH>
__global__ __launch_bounds__(256, 2)
void gemm_nt(const float* __restrict__ A, const float* __restrict__ W,
             const float* __restrict__ bias, float* __restrict__ C,
             int K, int F) {
    __shared__ float As[8][132];
    __shared__ float Bs[8][132];

    const int tid = threadIdx.x;
    const int tx = tid & 15;
    const int ty = tid >> 4;
    const int bm = blockIdx.y * 128;
    const int bn = blockIdx.x * 128;

    const int lrow = tid >> 1;
    const int lk   = (tid & 1) * 4;

    const float* Aptr = A + (size_t)(bm + lrow) * K + lk;
    const float* Wptr = W + (size_t)(bn + lrow) * K + lk;

    float acc[8][8];
    #pragma unroll
    for (int i = 0; i < 8; ++i)
        #pragma unroll
        for (int j = 0; j < 8; ++j) acc[i][j] = 0.f;

    for (int k0 = 0; k0 < K; k0 += 8) {
        float4 a = *(const float4*)(Aptr + k0);
        float4 b = *(const float4*)(Wptr + k0);
        As[lk + 0][lrow] = a.x; As[lk + 1][lrow] = a.y;
        As[lk + 2][lrow] = a.z; As[lk + 3][lrow] = a.w;
        Bs[lk + 0][lrow] = b.x; Bs[lk + 1][lrow] = b.y;
        Bs[lk + 2][lrow] = b.z; Bs[lk + 3][lrow] = b.w;
        __syncthreads();

        #pragma unroll
        for (int k = 0; k < 8; ++k) {
            float4 ra0 = *(const float4*)&As[k][ty * 8];
            float4 ra1 = *(const float4*)&As[k][ty * 8 + 4];
            float4 rb0 = *(const float4*)&Bs[k][tx * 8];
            float4 rb1 = *(const float4*)&Bs[k][tx * 8 + 4];
            float ra[8] = {ra0.x, ra0.y, ra0.z, ra0.w, ra1.x, ra1.y, ra1.z, ra1.w};
            float rb[8] = {rb0.x, rb0.y, rb0.z, rb0.w, rb1.x, rb1.y, rb1.z, rb1.w};
            #pragma unroll
            for (int i = 0; i < 8; ++i)
                #pragma unroll
                for (int j = 0; j < 8; ++j)
                    acc[i][j] = fmaf(ra[i], rb[j], acc[i][j]);
        }
        __syncthreads();
    }

    float bj[8];
    #pragma unroll
    for (int j = 0; j < 8; ++j) bj[j] = bias[bn + tx * 8 + j];

    #pragma unroll
    for (int i = 0; i < 8; ++i) {
        int row = bm + ty * 8 + i;
        float* Crow = C + (size_t)row * F + bn + tx * 8;
        float v[8];
        #pragma unroll
        for (int j = 0; j < 8; ++j) {
            float t = acc[i][j] + bj[j];
            v[j] = TANH ? tanhf(t) : t;
        }
        float4 v0 = {v[0], v[1], v[2], v[3]};
        float4 v1 = {v[4], v[5], v[6], v[7]};
        *(float4*)(Crow)     = v0;
        *(float4*)(Crow + 4) = v1;
    }
}

// ---------------- launch ---------------------------------------------------
extern "C" void kernel_launch(void* const* d_in, const int* in_sizes, int n_in,
                              void* d_out, int out_size) {
    const float* x     = (const float*)d_in[0];
    const float* gamma = (const float*)d_in[1];
    const float* beta  = (const float*)d_in[2];
    const float* W1    = (const float*)d_in[3];
    const float* b1    = (const float*)d_in[4];
    const float* W2    = (const float*)d_in[5];
    const float* b2    = (const float*)d_in[6];
    const float* Wf    = (const float*)d_in[7];
    const float* bf    = (const float*)d_in[8];

    float* out_main = (float*)d_out;                              // [N, 256]
    float* out_raw  = (float*)d_out + (size_t)N_ROWS * D_IN;      // [N, 256]

    float *part0, *T0, *part1, *Weff, *Wx, *beff;
    cudaGetSymbolAddress((void**)&part0, g_part0);
    cudaGetSymbolAddress((void**)&T0,    g_T0);
    cudaGetSymbolAddress((void**)&part1, g_part1);
    cudaGetSymbolAddress((void**)&Weff,  g_Weff);
    cudaGetSymbolAddress((void**)&Wx,    g_Wx);
    cudaGetSymbolAddress((void**)&beff,  g_beff);

    // --- BN statistics ---
    bn_zero<<<1, 256>>>();
    bn_reduce<<<256, 256>>>(x);
    bn_finalize<<<1, 256>>>(gamma, beta);

    // --- raw_feats = tanh(xn) ---
    bn_raw<<<(N_ROWS * D_IN / 4) / 256, 256>>>(x, out_raw);

    // --- collapse MLP: Weff = Wf @ W2 @ W1 ---
    // T0 = Wf[256,2048] @ W2[2048,512]  (split-K: 8 chunks of 256)
    gemm_nn_split<<<dim3(512 / 64, 256 / 64, 8), 256>>>(Wf, W2, part0, 256, 512, 2048, 256);
    reduce_splits<<<(256 * 512) / 256, 256>>>(part0, T0, 256 * 512, 8);
    // Weff = T0[256,512] @ W1[512,256]  (split-K: 4 chunks of 128)
    gemm_nn_split<<<dim3(256 / 64, 256 / 64, 4), 256>>>(T0, W1, part1, 256, 256, 512, 128);
    reduce_splits<<<(256 * 256) / 256, 256>>>(part1, Weff, 256 * 256, 4);

    // --- collapse biases: v2 = Wf@(W2@b1 + b2) + bf ---
    bias_chain1<<<F2 / 256, 256>>>(W2, b1, b2);
    bias_chain2<<<1, 256>>>(Wf, bf);

    // --- fold BN scale/shift into Weff/bias ---
    fold_bn<<<256, 256>>>();

    // --- out = tanh(x @ Wx^T + beff) ---
    gemm_nt<true><<<dim3(D_IN / 128, N_ROWS / 128), 256>>>(x, Wx, beff, out_main, D_IN, D_IN);
}

// round 4
// speedup vs baseline: 18.5671x; 2.3666x over previous
#include <cuda_runtime.h>
#include <cuda_bf16.h>
#include <math.h>

#define N_ROWS 65536
#define D_IN   256
#define F1     512
#define F2     2048
#define EPS    1e-5f

// ======================= scratch (device globals) ===========================
__device__ __align__(16) float g_sum[D_IN];
__device__ __align__(16) float g_sumsq[D_IN];
__device__ __align__(16) float g_scale[D_IN];
__device__ __align__(16) float g_shift[D_IN];
__device__ float g_part0[8 * 256 * 512];
__device__ float g_T0[256 * 512];
__device__ float g_part1[4 * 256 * 256];
__device__ float g_Weff[256 * 256];
__device__ __align__(16) __nv_bfloat16 g_Wxh[256 * 256];
__device__ __align__(16) __nv_bfloat16 g_Wxl[256 * 256];
__device__ float g_v1[F2];
__device__ float g_v2[D_IN];
__device__ __align__(16) float g_beff[D_IN];

// ======================= BN stats ==========================================
__global__ void bn_zero() {
    g_sum[threadIdx.x]   = 0.f;
    g_sumsq[threadIdx.x] = 0.f;
}

__global__ void bn_reduce(const float* __restrict__ x) {
    const int col = threadIdx.x;
    const int rows_per_block = N_ROWS / gridDim.x;
    size_t base = (size_t)blockIdx.x * rows_per_block * D_IN + col;
    float s = 0.f, sq = 0.f;
    #pragma unroll 8
    for (int r = 0; r < rows_per_block; ++r) {
        float v = x[base + (size_t)r * D_IN];
        s += v; sq += v * v;
    }
    atomicAdd(&g_sum[col], s);
    atomicAdd(&g_sumsq[col], sq);
}

__global__ void bn_finalize(const float* __restrict__ gamma,
                            const float* __restrict__ beta) {
    int j = threadIdx.x;
    float inv_n = 1.0f / (float)N_ROWS;
    float mu  = g_sum[j] * inv_n;
    float var = g_sumsq[j] * inv_n - mu * mu;
    float sc  = gamma[j] * rsqrtf(var + EPS);
    g_scale[j] = sc;
    g_shift[j] = beta[j] - mu * sc;
}

// ======================= collapse chain ====================================
__global__ void gemm_nn_split(const float* __restrict__ A,
                              const float* __restrict__ B,
                              float* __restrict__ P,
                              int M, int N, int K, int kchunk) {
    __shared__ float As[16][64];
    __shared__ float Bs[16][65];
    const int tid = threadIdx.x;
    const int tx = tid & 15, ty = tid >> 4;
    const int bn = blockIdx.x * 64, bm = blockIdx.y * 64;
    const int k0 = blockIdx.z * kchunk;

    float acc[4][4];
    #pragma unroll
    for (int i = 0; i < 4; ++i)
        #pragma unroll
        for (int j = 0; j < 4; ++j) acc[i][j] = 0.f;

    for (int kb = k0; kb < k0 + kchunk; kb += 16) {
        #pragma unroll
        for (int t = 0; t < 4; ++t) {
            int idx = tid * 4 + t;
            int r = idx >> 4, kk = idx & 15;
            As[kk][r] = A[(size_t)(bm + r) * K + kb + kk];
        }
        #pragma unroll
        for (int t = 0; t < 4; ++t) {
            int idx = tid + t * 256;
            int c = idx & 63, kk = idx >> 6;
            Bs[kk][c] = B[(size_t)(kb + kk) * N + bn + c];
        }
        __syncthreads();
        #pragma unroll
        for (int kk = 0; kk < 16; ++kk) {
            float a[4], b[4];
            #pragma unroll
            for (int i = 0; i < 4; ++i) a[i] = As[kk][ty * 4 + i];
            #pragma unroll
            for (int j = 0; j < 4; ++j) b[j] = Bs[kk][tx * 4 + j];
            #pragma unroll
            for (int i = 0; i < 4; ++i)
                #pragma unroll
                for (int j = 0; j < 4; ++j)
                    acc[i][j] = fmaf(a[i], b[j], acc[i][j]);
        }
        __syncthreads();
    }
    float* Pb = P + (size_t)blockIdx.z * M * N;
    #pragma unroll
    for (int i = 0; i < 4; ++i)
        #pragma unroll
        for (int j = 0; j < 4; ++j)
            Pb[(size_t)(bm + ty * 4 + i) * N + bn + tx * 4 + j] = acc[i][j];
}

__global__ void reduce_splits(const float* __restrict__ P, float* __restrict__ C,
                              int MN, int S) {
    int i = blockIdx.x * 256 + threadIdx.x;
    if (i >= MN) return;
    float s = 0.f;
    for (int k = 0; k < S; ++k) s += P[(size_t)k * MN + i];
    C[i] = s;
}

// warp-per-row, coalesced: v1[row] = dot(W2[row,:], b1) + b2[row]
__global__ void bias_chain1(const float* __restrict__ W2, const float* __restrict__ b1,
                            const float* __restrict__ b2) {
    int row = blockIdx.x * 8 + (threadIdx.x >> 5);
    int lid = threadIdx.x & 31;
    const float* r = W2 + (size_t)row * F1;
    float s = 0.f;
    #pragma unroll
    for (int k = lid; k < F1; k += 32) s = fmaf(r[k], b1[k], s);
    #pragma unroll
    for (int o = 16; o > 0; o >>= 1) s += __shfl_down_sync(0xFFFFFFFFu, s, o);
    if (lid == 0) g_v1[row] = s + b2[row];
}

// block-per-row, coalesced: v2[row] = dot(Wf[row,:], v1) + bf[row]
__global__ void bias_chain2(const float* __restrict__ Wf, const float* __restrict__ bf) {
    int row = blockIdx.x;
    int t = threadIdx.x;
    const float* r = Wf + (size_t)row * F2;
    float s = 0.f;
    #pragma unroll
    for (int k = t; k < F2; k += 256) s = fmaf(r[k], g_v1[k], s);
    __shared__ float red[256];
    red[t] = s;
    __syncthreads();
    for (int o = 128; o > 0; o >>= 1) {
        if (t < o) red[t] += red[t + o];
        __syncthreads();
    }
    if (t == 0) g_v2[row] = red[0] + bf[row];
}

// Wx = Weff * scale[col] -> bf16 hi/lo split;  beff = v2 + Weff @ shift
__global__ void fold_bn() {
    int i = blockIdx.x;
    int t = threadIdx.x;
    float w = g_Weff[i * D_IN + t];
    float wx = w * g_scale[t];
    __nv_bfloat16 hi = __float2bfloat16_rn(wx);
    float lo = wx - __bfloat162float(hi);
    g_Wxh[i * D_IN + t] = hi;
    g_Wxl[i * D_IN + t] = __float2bfloat16_rn(lo);
    __shared__ float red[256];
    red[t] = w * g_shift[t];
    __syncthreads();
    for (int o = 128; o > 0; o >>= 1) {
        if (t < o) red[t] += red[t + o];
        __syncthreads();
    }
    if (t == 0) g_beff[i] = g_v2[i] + red[0];
}

// ======================= fused HMMA main GEMM ==============================
// out = tanh(x @ Wx^T + beff) via mma.sync bf16 x3 split.
// CTA: 128 rows x 128 cols, K=256 chunked by 64. raw_feats fused (bn==0 CTAs).
#define KSTRIDE 72                       // padded bf16 row stride (elems)
#define A_HI 0
#define A_LO (128 * KSTRIDE * 2)
#define B_HI (2 * 128 * KSTRIDE * 2)
#define B_LO (3 * 128 * KSTRIDE * 2)
#define SMEM_MAIN (4 * 128 * KSTRIDE * 2)

__device__ __forceinline__ unsigned smem_u32(const void* p) {
    unsigned a;
    asm("{ .reg .u64 t; cvta.to.shared.u64 t, %1; cvt.u32.u64 %0, t; }"
        : "=r"(a) : "l"(p));
    return a;
}

__device__ __forceinline__ void ldsm_x4(unsigned r[4], unsigned addr) {
    asm volatile("ldmatrix.sync.aligned.m8n8.x4.shared.b16 {%0,%1,%2,%3}, [%4];"
                 : "=r"(r[0]), "=r"(r[1]), "=r"(r[2]), "=r"(r[3]) : "r"(addr));
}

__device__ __forceinline__ void mma_bf16(float c[4], const unsigned a[4],
                                         unsigned b0, unsigned b1) {
    asm volatile(
        "mma.sync.aligned.m16n8k16.row.col.f32.bf16.bf16.f32 "
        "{%0,%1,%2,%3}, {%4,%5,%6,%7}, {%8,%9}, {%0,%1,%2,%3};"
        : "+f"(c[0]), "+f"(c[1]), "+f"(c[2]), "+f"(c[3])
        : "r"(a[0]), "r"(a[1]), "r"(a[2]), "r"(a[3]), "r"(b0), "r"(b1));
}

__global__ __launch_bounds__(256)
void fused_main(const float* __restrict__ x,
                const __nv_bfloat16* __restrict__ Wxh,
                const __nv_bfloat16* __restrict__ Wxl,
                float* __restrict__ out_main,
                float* __restrict__ raw_out) {
    extern __shared__ __align__(16) char smem[];
    const unsigned sb = smem_u32(smem);
    const int tid = threadIdx.x;
    const int wid = tid >> 5, lane = tid & 31;
    const int warp_m = wid & 3;          // 4 warps in M (32 rows each)
    const int warp_n = wid >> 2;         // 2 warps in N (64 cols each)
    const int bm = blockIdx.y * 128;
    const int bn = blockIdx.x * 128;
    const bool do_raw = (blockIdx.x == 0);

    const int arow  = tid >> 1;          // 0..127
    const int ahalf = (tid & 1) * 32;    // 0 or 32

    float acc[2][8][4];
    #pragma unroll
    for (int m = 0; m < 2; ++m)
        #pragma unroll
        for (int n = 0; n < 8; ++n)
            #pragma unroll
            for (int q = 0; q < 4; ++q) acc[m][n][q] = 0.f;

    for (int c = 0; c < 4; ++c) {
        const int kc = c * 64;
        __syncthreads();

        // ---- A: load x fp32, split bf16 hi/lo; optional fused raw_feats ----
        {
            const float* xp = x + (size_t)(bm + arow) * D_IN + kc + ahalf;
            #pragma unroll
            for (int j = 0; j < 8; ++j) {
                float4 v = *(const float4*)(xp + j * 4);
                __nv_bfloat162 h01 = __floats2bfloat162_rn(v.x, v.y);
                __nv_bfloat162 h23 = __floats2bfloat162_rn(v.z, v.w);
                float l0 = v.x - __bfloat162float(h01.x);
                float l1 = v.y - __bfloat162float(h01.y);
                float l2 = v.z - __bfloat162float(h23.x);
                float l3 = v.w - __bfloat162float(h23.y);
                __nv_bfloat162 lo01 = __floats2bfloat162_rn(l0, l1);
                __nv_bfloat162 lo23 = __floats2bfloat162_rn(l2, l3);
                unsigned boff = (unsigned)((arow * KSTRIDE + ahalf + j * 4) * 2);
                *(unsigned*)(smem + A_HI + boff)     = *(unsigned*)&h01;
                *(unsigned*)(smem + A_HI + boff + 4) = *(unsigned*)&h23;
                *(unsigned*)(smem + A_LO + boff)     = *(unsigned*)&lo01;
                *(unsigned*)(smem + A_LO + boff + 4) = *(unsigned*)&lo23;
                if (do_raw) {
                    const int col = kc + ahalf + j * 4;
                    float4 sc = *(const float4*)(g_scale + col);
                    float4 sh = *(const float4*)(g_shift + col);
                    float4 t;
                    t.x = tanhf(fmaf(v.x, sc.x, sh.x));
                    t.y = tanhf(fmaf(v.y, sc.y, sh.y));
                    t.z = tanhf(fmaf(v.z, sc.z, sh.z));
                    t.w = tanhf(fmaf(v.w, sc.w, sh.w));
                    *(float4*)(raw_out + (size_t)(bm + arow) * D_IN + col) = t;
                }
            }
        }
        // ---- B: Wx hi/lo bf16 chunk (rows bn..bn+127, cols kc..kc+63) ----
        {
            const size_t wb = (size_t)(bn + arow) * D_IN + kc + ahalf;
            #pragma unroll
            for (int j = 0; j < 4; ++j) {
                unsigned boff = (unsigned)((arow * KSTRIDE + ahalf + j * 8) * 2);
                *(uint4*)(smem + B_HI + boff) = *(const uint4*)(Wxh + wb + j * 8);
                *(uint4*)(smem + B_LO + boff) = *(const uint4*)(Wxl + wb + j * 8);
            }
        }
        __syncthreads();

        // ---- compute: 4 ksteps of k16 ----
        #pragma unroll
        for (int ks = 0; ks < 4; ++ks) {
            const int k0 = ks * 16;
            unsigned ah[2][4], al[2][4];
            #pragma unroll
            for (int m = 0; m < 2; ++m) {
                int row = warp_m * 32 + m * 16 + (lane & 15);
                int col = k0 + (lane >> 4) * 8;
                unsigned off = (unsigned)((row * KSTRIDE + col) * 2);
                ldsm_x4(ah[m], sb + A_HI + off);
                ldsm_x4(al[m], sb + A_LO + off);
            }
            #pragma unroll
            for (int g = 0; g < 4; ++g) {
                int nrow = warp_n * 64 + g * 16 + (lane & 15);
                int col = k0 + (lane >> 4) * 8;
                unsigned off = (unsigned)((nrow * KSTRIDE + col) * 2);
                unsigned bh[4], bl[4];
                ldsm_x4(bh, sb + B_HI + off);
                ldsm_x4(bl, sb + B_LO + off);
                #pragma unroll
                for (int m = 0; m < 2; ++m) {
                    #pragma unroll
                    for (int s = 0; s < 2; ++s) {
                        float* a = acc[m][g * 2 + s];
                        mma_bf16(a, ah[m], bh[s], bh[s + 2]);
                        mma_bf16(a, ah[m], bl[s], bl[s + 2]);
                        mma_bf16(a, al[m], bh[s], bh[s + 2]);
                    }
                }
            }
        }
    }

    // ---- epilogue: bias + tanh + store ----
    const int gr = lane >> 2;            // 0..7
    const int gc = (lane & 3) * 2;       // 0,2,4,6
    #pragma unroll
    for (int m = 0; m < 2; ++m) {
        #pragma unroll
        for (int n = 0; n < 8; ++n) {
            int col = bn + warp_n * 64 + n * 8 + gc;
            float2 bv = *(const float2*)(g_beff + col);
            int r0 = bm + warp_m * 32 + m * 16 + gr;
            float2 o0, o1;
            o0.x = tanhf(acc[m][n][0] + bv.x);
            o0.y = tanhf(acc[m][n][1] + bv.y);
            o1.x = tanhf(acc[m][n][2] + bv.x);
            o1.y = tanhf(acc[m][n][3] + bv.y);
            *(float2*)(out_main + (size_t)r0 * D_IN + col)       = o0;
            *(float2*)(out_main + (size_t)(r0 + 8) * D_IN + col) = o1;
        }
    }
}

// ======================= launch ============================================
extern "C" void kernel_launch(void* const* d_in, const int* in_sizes, int n_in,
                              void* d_out, int out_size) {
    const float* x     = (const float*)d_in[0];
    const float* gamma = (const float*)d_in[1];
    const float* beta  = (const float*)d_in[2];
    const float* W1    = (const float*)d_in[3];
    const float* b1    = (const float*)d_in[4];
    const float* W2    = (const float*)d_in[5];
    const float* b2    = (const float*)d_in[6];
    const float* Wf    = (const float*)d_in[7];
    const float* bf    = (const float*)d_in[8];

    float* out_main = (float*)d_out;
    float* out_raw  = (float*)d_out + (size_t)N_ROWS * D_IN;

    float *part0, *T0, *part1, *Weff;
    __nv_bfloat16 *Wxh, *Wxl;
    cudaGetSymbolAddress((void**)&part0, g_part0);
    cudaGetSymbolAddress((void**)&T0,    g_T0);
    cudaGetSymbolAddress((void**)&part1, g_part1);
    cudaGetSymbolAddress((void**)&Weff,  g_Weff);
    cudaGetSymbolAddress((void**)&Wxh,   g_Wxh);
    cudaGetSymbolAddress((void**)&Wxl,   g_Wxl);

    static int smem_set = 0;
    if (!smem_set) {
        cudaFuncSetAttribute(fused_main, cudaFuncAttributeMaxDynamicSharedMemorySize,
                             SMEM_MAIN);
        smem_set = 1;
    }

    // BN statistics
    bn_zero<<<1, 256>>>();
    bn_reduce<<<256, 256>>>(x);
    bn_finalize<<<1, 256>>>(gamma, beta);

    // collapse: Weff = Wf @ W2 @ W1
    gemm_nn_split<<<dim3(512 / 64, 256 / 64, 8), 256>>>(Wf, W2, part0, 256, 512, 2048, 256);
    reduce_splits<<<(256 * 512) / 256, 256>>>(part0, T0, 256 * 512, 8);
    gemm_nn_split<<<dim3(256 / 64, 256 / 64, 4), 256>>>(T0, W1, part1, 256, 256, 512, 128);
    reduce_splits<<<(256 * 256) / 256, 256>>>(part1, Weff, 256 * 256, 4);

    // collapse biases
    bias_chain1<<<F2 / 8, 256>>>(W2, b1, b2);
    bias_chain2<<<D_IN, 256>>>(Wf, bf);

    // fold BN into weights (bf16 hi/lo) + bias
    fold_bn<<<256, 256>>>();

    // fused main: out = tanh(x @ Wx^T + beff), raw = tanh(x*scale + shift)
    fused_main<<<dim3(2, N_ROWS / 128), 256, SMEM_MAIN>>>(x, Wxh, Wxl, out_main, out_raw);
}

// round 5
// speedup vs baseline: 19.5783x; 1.0545x over previous
#include <cuda_runtime.h>
#include <cuda_bf16.h>
#include <math.h>

#define N_ROWS 65536
#define D_IN   256
#define F1     512
#define F2     2048
#define EPS    1e-5f

// ======================= scratch (device globals) ===========================
__device__ __align__(16) float g_sum[D_IN];
__device__ __align__(16) float g_sumsq[D_IN];
__device__ __align__(16) float g_scale[D_IN];
__device__ __align__(16) float g_shift[D_IN];
__device__ float g_part0[16 * 256 * 512];
__device__ float g_T0[256 * 512];
__device__ float g_part1[16 * 256 * 256];
__device__ float g_Weff[256 * 256];
__device__ __align__(16) __nv_bfloat16 g_Wxh[256 * 256];
__device__ __align__(16) __nv_bfloat16 g_Wxl[256 * 256];
__device__ float g_v1[F2];
__device__ float g_v2[D_IN];
__device__ __align__(16) float g_beff[D_IN];

// ======================= BN stats ==========================================
__global__ void bn_zero() {
    g_sum[threadIdx.x]   = 0.f;
    g_sumsq[threadIdx.x] = 0.f;
}

__global__ void bn_reduce(const float* __restrict__ x) {
    const int col = threadIdx.x;
    const int rows_per_block = N_ROWS / gridDim.x;
    size_t base = (size_t)blockIdx.x * rows_per_block * D_IN + col;
    float s = 0.f, sq = 0.f;
    #pragma unroll 8
    for (int r = 0; r < rows_per_block; ++r) {
        float v = x[base + (size_t)r * D_IN];
        s += v; sq += v * v;
    }
    atomicAdd(&g_sum[col], s);
    atomicAdd(&g_sumsq[col], sq);
}

__global__ void bn_finalize(const float* __restrict__ gamma,
                            const float* __restrict__ beta) {
    int j = threadIdx.x;
    float inv_n = 1.0f / (float)N_ROWS;
    float mu  = g_sum[j] * inv_n;
    float var = g_sumsq[j] * inv_n - mu * mu;
    float sc  = gamma[j] * rsqrtf(var + EPS);
    g_scale[j] = sc;
    g_shift[j] = beta[j] - mu * sc;
}

// ======================= collapse chain ====================================
__global__ void gemm_nn_split(const float* __restrict__ A,
                              const float* __restrict__ B,
                              float* __restrict__ P,
                              int M, int N, int K, int kchunk) {
    __shared__ float As[16][64];
    __shared__ float Bs[16][65];
    const int tid = threadIdx.x;
    const int tx = tid & 15, ty = tid >> 4;
    const int bn = blockIdx.x * 64, bm = blockIdx.y * 64;
    const int k0 = blockIdx.z * kchunk;

    float acc[4][4];
    #pragma unroll
    for (int i = 0; i < 4; ++i)
        #pragma unroll
        for (int j = 0; j < 4; ++j) acc[i][j] = 0.f;

    for (int kb = k0; kb < k0 + kchunk; kb += 16) {
        #pragma unroll
        for (int t = 0; t < 4; ++t) {
            int idx = tid * 4 + t;
            int r = idx >> 4, kk = idx & 15;
            As[kk][r] = A[(size_t)(bm + r) * K + kb + kk];
        }
        #pragma unroll
        for (int t = 0; t < 4; ++t) {
            int idx = tid + t * 256;
            int c = idx & 63, kk = idx >> 6;
            Bs[kk][c] = B[(size_t)(kb + kk) * N + bn + c];
        }
        __syncthreads();
        #pragma unroll
        for (int kk = 0; kk < 16; ++kk) {
            float a[4], b[4];
            #pragma unroll
            for (int i = 0; i < 4; ++i) a[i] = As[kk][ty * 4 + i];
            #pragma unroll
            for (int j = 0; j < 4; ++j) b[j] = Bs[kk][tx * 4 + j];
            #pragma unroll
            for (int i = 0; i < 4; ++i)
                #pragma unroll
                for (int j = 0; j < 4; ++j)
                    acc[i][j] = fmaf(a[i], b[j], acc[i][j]);
        }
        __syncthreads();
    }
    float* Pb = P + (size_t)blockIdx.z * M * N;
    #pragma unroll
    for (int i = 0; i < 4; ++i)
        #pragma unroll
        for (int j = 0; j < 4; ++j)
            Pb[(size_t)(bm + ty * 4 + i) * N + bn + tx * 4 + j] = acc[i][j];
}

__global__ void reduce_splits(const float* __restrict__ P, float* __restrict__ C,
                              int MN, int S) {
    int i = blockIdx.x * 256 + threadIdx.x;
    if (i >= MN) return;
    float s = 0.f;
    for (int k = 0; k < S; ++k) s += P[(size_t)k * MN + i];
    C[i] = s;
}

// warp-per-row, coalesced: v1[row] = dot(W2[row,:], b1) + b2[row]
__global__ void bias_chain1(const float* __restrict__ W2, const float* __restrict__ b1,
                            const float* __restrict__ b2) {
    int row = blockIdx.x * 8 + (threadIdx.x >> 5);
    int lid = threadIdx.x & 31;
    const float* r = W2 + (size_t)row * F1;
    float s = 0.f;
    #pragma unroll
    for (int k = lid; k < F1; k += 32) s = fmaf(r[k], b1[k], s);
    #pragma unroll
    for (int o = 16; o > 0; o >>= 1) s += __shfl_down_sync(0xFFFFFFFFu, s, o);
    if (lid == 0) g_v1[row] = s + b2[row];
}

// block-per-row, coalesced: v2[row] = dot(Wf[row,:], v1) + bf[row]
__global__ void bias_chain2(const float* __restrict__ Wf, const float* __restrict__ bf) {
    int row = blockIdx.x;
    int t = threadIdx.x;
    const float* r = Wf + (size_t)row * F2;
    float s = 0.f;
    #pragma unroll
    for (int k = t; k < F2; k += 256) s = fmaf(r[k], g_v1[k], s);
    __shared__ float red[256];
    red[t] = s;
    __syncthreads();
    for (int o = 128; o > 0; o >>= 1) {
        if (t < o) red[t] += red[t + o];
        __syncthreads();
    }
    if (t == 0) g_v2[row] = red[0] + bf[row];
}

// Wx = Weff * scale[col] -> bf16 hi/lo split;  beff = v2 + Weff @ shift
__global__ void fold_bn() {
    int i = blockIdx.x;
    int t = threadIdx.x;
    float w = g_Weff[i * D_IN + t];
    float wx = w * g_scale[t];
    __nv_bfloat16 hi = __float2bfloat16_rn(wx);
    float lo = wx - __bfloat162float(hi);
    g_Wxh[i * D_IN + t] = hi;
    g_Wxl[i * D_IN + t] = __float2bfloat16_rn(lo);
    __shared__ float red[256];
    red[t] = w * g_shift[t];
    __syncthreads();
    for (int o = 128; o > 0; o >>= 1) {
        if (t < o) red[t] += red[t + o];
        __syncthreads();
    }
    if (t == 0) g_beff[i] = g_v2[i] + red[0];
}

// ======================= fused HMMA main GEMM ==============================
#define KSTRIDE 72
#define A_HI 0
#define A_LO (128 * KSTRIDE * 2)
#define B_HI (2 * 128 * KSTRIDE * 2)
#define B_LO (3 * 128 * KSTRIDE * 2)
#define SMEM_MAIN (4 * 128 * KSTRIDE * 2)

__device__ __forceinline__ unsigned smem_u32(const void* p) {
    unsigned a;
    asm("{ .reg .u64 t; cvta.to.shared.u64 t, %1; cvt.u32.u64 %0, t; }"
        : "=r"(a) : "l"(p));
    return a;
}

__device__ __forceinline__ void ldsm_x4(unsigned r[4], unsigned addr) {
    asm volatile("ldmatrix.sync.aligned.m8n8.x4.shared.b16 {%0,%1,%2,%3}, [%4];"
                 : "=r"(r[0]), "=r"(r[1]), "=r"(r[2]), "=r"(r[3]) : "r"(addr));
}

__device__ __forceinline__ void mma_bf16(float c[4], const unsigned a[4],
                                         unsigned b0, unsigned b1) {
    asm volatile(
        "mma.sync.aligned.m16n8k16.row.col.f32.bf16.bf16.f32 "
        "{%0,%1,%2,%3}, {%4,%5,%6,%7}, {%8,%9}, {%0,%1,%2,%3};"
        : "+f"(c[0]), "+f"(c[1]), "+f"(c[2]), "+f"(c[3])
        : "r"(a[0]), "r"(a[1]), "r"(a[2]), "r"(a[3]), "r"(b0), "r"(b1));
}

__global__ __launch_bounds__(256)
void fused_main(const float* __restrict__ x,
                const __nv_bfloat16* __restrict__ Wxh,
                const __nv_bfloat16* __restrict__ Wxl,
                float* __restrict__ out_main,
                float* __restrict__ raw_out) {
    extern __shared__ __align__(16) char smem[];
    const unsigned sb = smem_u32(smem);
    const int tid = threadIdx.x;
    const int wid = tid >> 5, lane = tid & 31;
    const int warp_m = wid & 3;
    const int warp_n = wid >> 2;
    const int bm = blockIdx.y * 128;
    const int bn = blockIdx.x * 128;
    const bool do_raw = (blockIdx.x == 0);

    const int arow  = tid >> 1;
    const int ahalf = (tid & 1) * 32;

    float acc[2][8][4];
    #pragma unroll
    for (int m = 0; m < 2; ++m)
        #pragma unroll
        for (int n = 0; n < 8; ++n)
            #pragma unroll
            for (int q = 0; q < 4; ++q) acc[m][n][q] = 0.f;

    for (int c = 0; c < 4; ++c) {
        const int kc = c * 64;
        __syncthreads();

        {
            const float* xp = x + (size_t)(bm + arow) * D_IN + kc + ahalf;
            #pragma unroll
            for (int j = 0; j < 8; ++j) {
                float4 v = *(const float4*)(xp + j * 4);
                __nv_bfloat162 h01 = __floats2bfloat162_rn(v.x, v.y);
                __nv_bfloat162 h23 = __floats2bfloat162_rn(v.z, v.w);
                float l0 = v.x - __bfloat162float(h01.x);
                float l1 = v.y - __bfloat162float(h01.y);
                float l2 = v.z - __bfloat162float(h23.x);
                float l3 = v.w - __bfloat162float(h23.y);
                __nv_bfloat162 lo01 = __floats2bfloat162_rn(l0, l1);
                __nv_bfloat162 lo23 = __floats2bfloat162_rn(l2, l3);
                unsigned boff = (unsigned)((arow * KSTRIDE + ahalf + j * 4) * 2);
                *(unsigned*)(smem + A_HI + boff)     = *(unsigned*)&h01;
                *(unsigned*)(smem + A_HI + boff + 4) = *(unsigned*)&h23;
                *(unsigned*)(smem + A_LO + boff)     = *(unsigned*)&lo01;
                *(unsigned*)(smem + A_LO + boff + 4) = *(unsigned*)&lo23;
                if (do_raw) {
                    const int col = kc + ahalf + j * 4;
                    float4 sc = *(const float4*)(g_scale + col);
                    float4 sh = *(const float4*)(g_shift + col);
                    float4 t;
                    t.x = tanhf(fmaf(v.x, sc.x, sh.x));
                    t.y = tanhf(fmaf(v.y, sc.y, sh.y));
                    t.z = tanhf(fmaf(v.z, sc.z, sh.z));
                    t.w = tanhf(fmaf(v.w, sc.w, sh.w));
                    *(float4*)(raw_out + (size_t)(bm + arow) * D_IN + col) = t;
                }
            }
        }
        {
            const size_t wb = (size_t)(bn + arow) * D_IN + kc + ahalf;
            #pragma unroll
            for (int j = 0; j < 4; ++j) {
                unsigned boff = (unsigned)((arow * KSTRIDE + ahalf + j * 8) * 2);
                *(uint4*)(smem + B_HI + boff) = *(const uint4*)(Wxh + wb + j * 8);
                *(uint4*)(smem + B_LO + boff) = *(const uint4*)(Wxl + wb + j * 8);
            }
        }
        __syncthreads();

        #pragma unroll
        for (int ks = 0; ks < 4; ++ks) {
            const int k0 = ks * 16;
            unsigned ah[2][4], al[2][4];
            #pragma unroll
            for (int m = 0; m < 2; ++m) {
                int row = warp_m * 32 + m * 16 + (lane & 15);
                int col = k0 + (lane >> 4) * 8;
                unsigned off = (unsigned)((row * KSTRIDE + col) * 2);
                ldsm_x4(ah[m], sb + A_HI + off);
                ldsm_x4(al[m], sb + A_LO + off);
            }
            #pragma unroll
            for (int g = 0; g < 4; ++g) {
                int nrow = warp_n * 64 + g * 16 + (lane & 15);
                int col = k0 + (lane >> 4) * 8;
                unsigned off = (unsigned)((nrow * KSTRIDE + col) * 2);
                unsigned bh[4], bl[4];
                ldsm_x4(bh, sb + B_HI + off);
                ldsm_x4(bl, sb + B_LO + off);
                #pragma unroll
                for (int m = 0; m < 2; ++m) {
                    #pragma unroll
                    for (int s = 0; s < 2; ++s) {
                        float* a = acc[m][g * 2 + s];
                        mma_bf16(a, ah[m], bh[s], bh[s + 2]);
                        mma_bf16(a, ah[m], bl[s], bl[s + 2]);
                        mma_bf16(a, al[m], bh[s], bh[s + 2]);
                    }
                }
            }
        }
    }

    const int gr = lane >> 2;
    const int gc = (lane & 3) * 2;
    #pragma unroll
    for (int m = 0; m < 2; ++m) {
        #pragma unroll
        for (int n = 0; n < 8; ++n) {
            int col = bn + warp_n * 64 + n * 8 + gc;
            float2 bv = *(const float2*)(g_beff + col);
            int r0 = bm + warp_m * 32 + m * 16 + gr;
            float2 o0, o1;
            o0.x = tanhf(acc[m][n][0] + bv.x);
            o0.y = tanhf(acc[m][n][1] + bv.y);
            o1.x = tanhf(acc[m][n][2] + bv.x);
            o1.y = tanhf(acc[m][n][3] + bv.y);
            *(float2*)(out_main + (size_t)r0 * D_IN + col)       = o0;
            *(float2*)(out_main + (size_t)(r0 + 8) * D_IN + col) = o1;
        }
    }
}

// ======================= launch ============================================
extern "C" void kernel_launch(void* const* d_in, const int* in_sizes, int n_in,
                              void* d_out, int out_size) {
    const float* x     = (const float*)d_in[0];
    const float* gamma = (const float*)d_in[1];
    const float* beta  = (const float*)d_in[2];
    const float* W1    = (const float*)d_in[3];
    const float* b1    = (const float*)d_in[4];
    const float* W2    = (const float*)d_in[5];
    const float* b2    = (const float*)d_in[6];
    const float* Wf    = (const float*)d_in[7];
    const float* bf    = (const float*)d_in[8];

    float* out_main = (float*)d_out;
    float* out_raw  = (float*)d_out + (size_t)N_ROWS * D_IN;

    float *part0, *T0, *part1, *Weff;
    __nv_bfloat16 *Wxh, *Wxl;
    cudaGetSymbolAddress((void**)&part0, g_part0);
    cudaGetSymbolAddress((void**)&T0,    g_T0);
    cudaGetSymbolAddress((void**)&part1, g_part1);
    cudaGetSymbolAddress((void**)&Weff,  g_Weff);
    cudaGetSymbolAddress((void**)&Wxh,   g_Wxh);
    cudaGetSymbolAddress((void**)&Wxl,   g_Wxl);

    static cudaStream_t sBN = nullptr, sBias = nullptr;
    static cudaEvent_t evFork = nullptr, evBN = nullptr, evBias = nullptr;
    static int init_done = 0;
    if (!init_done) {
        cudaFuncSetAttribute(fused_main, cudaFuncAttributeMaxDynamicSharedMemorySize,
                             SMEM_MAIN);
        cudaStreamCreateWithFlags(&sBN,   cudaStreamNonBlocking);
        cudaStreamCreateWithFlags(&sBias, cudaStreamNonBlocking);
        cudaEventCreateWithFlags(&evFork, cudaEventDisableTiming);
        cudaEventCreateWithFlags(&evBN,   cudaEventDisableTiming);
        cudaEventCreateWithFlags(&evBias, cudaEventDisableTiming);
        init_done = 1;
    }

    // ---- fork: BN stats and bias chain run concurrently with weight collapse
    cudaEventRecord(evFork, 0);
    cudaStreamWaitEvent(sBN,   evFork, 0);
    cudaStreamWaitEvent(sBias, evFork, 0);

    // branch BN (stream sBN)
    bn_zero<<<1, 256, 0, sBN>>>();
    bn_reduce<<<256, 256, 0, sBN>>>(x);
    bn_finalize<<<1, 256, 0, sBN>>>(gamma, beta);
    cudaEventRecord(evBN, sBN);

    // branch bias (stream sBias)
    bias_chain1<<<F2 / 8, 256, 0, sBias>>>(W2, b1, b2);
    bias_chain2<<<D_IN, 256, 0, sBias>>>(Wf, bf);
    cudaEventRecord(evBias, sBias);

    // branch weight collapse (default stream): Weff = Wf @ W2 @ W1
    gemm_nn_split<<<dim3(512 / 64, 256 / 64, 16), 256>>>(Wf, W2, part0, 256, 512, 2048, 128);
    reduce_splits<<<(256 * 512) / 256, 256>>>(part0, T0, 256 * 512, 16);
    gemm_nn_split<<<dim3(256 / 64, 256 / 64, 16), 256>>>(T0, W1, part1, 256, 256, 512, 32);
    reduce_splits<<<(256 * 256) / 256, 256>>>(part1, Weff, 256 * 256, 16);

    // ---- join
    cudaStreamWaitEvent(0, evBN, 0);
    cudaStreamWaitEvent(0, evBias, 0);

    // fold BN into weights + bias
    fold_bn<<<256, 256>>>();

    // fused main: out = tanh(x @ Wx^T + beff), raw = tanh(x*scale + shift)
    fused_main<<<dim3(2, N_ROWS / 128), 256, SMEM_MAIN>>>(x, Wxh, Wxl, out_main, out_raw);
}

// round 6
// speedup vs baseline: 27.1495x; 1.3867x over previous
#include <cuda_runtime.h>
#include <cuda_bf16.h>
#include <math.h>

#define N_ROWS 65536
#define D_IN   256
#define F1     512
#define F2     2048
#define EPS    1e-5f

// ======================= scratch (device globals) ===========================
__device__ __align__(16) float g_sum[D_IN];
__device__ __align__(16) float g_sumsq[D_IN];
__device__ __align__(16) float g_scale[D_IN];
__device__ __align__(16) float g_shift[D_IN];
__device__ float g_part0[16 * 256 * 512];
__device__ float g_T0[256 * 512];
__device__ float g_part1[16 * 256 * 256];
__device__ float g_Weff[256 * 256];
__device__ __align__(16) __nv_bfloat16 g_Wxh[256 * 256];
__device__ __align__(16) __nv_bfloat16 g_Wxl[256 * 256];
__device__ float g_v1[F2];
__device__ float g_v2[D_IN];
__device__ __align__(16) float g_beff[D_IN];

__device__ __forceinline__ float tanh_fast(float v) {
    float r;
    asm("tanh.approx.f32 %0, %1;" : "=f"(r) : "f"(v));
    return r;
}

// ======================= BN stats ==========================================
__global__ void bn_zero() {
    g_sum[threadIdx.x]   = 0.f;
    g_sumsq[threadIdx.x] = 0.f;
}

__global__ void bn_reduce(const float* __restrict__ x) {
    const int col = threadIdx.x;
    const int rows_per_block = N_ROWS / gridDim.x;
    size_t base = (size_t)blockIdx.x * rows_per_block * D_IN + col;
    float s = 0.f, sq = 0.f;
    #pragma unroll 8
    for (int r = 0; r < rows_per_block; ++r) {
        float v = x[base + (size_t)r * D_IN];
        s += v; sq += v * v;
    }
    atomicAdd(&g_sum[col], s);
    atomicAdd(&g_sumsq[col], sq);
}

__global__ void bn_finalize(const float* __restrict__ gamma,
                            const float* __restrict__ beta) {
    int j = threadIdx.x;
    float inv_n = 1.0f / (float)N_ROWS;
    float mu  = g_sum[j] * inv_n;
    float var = g_sumsq[j] * inv_n - mu * mu;
    float sc  = gamma[j] * rsqrtf(var + EPS);
    g_scale[j] = sc;
    g_shift[j] = beta[j] - mu * sc;
}

// raw_feats = tanh(x*scale + shift), MUFU tanh, float4
__global__ void bn_raw(const float* __restrict__ x, float* __restrict__ raw_out) {
    size_t i4 = (size_t)blockIdx.x * blockDim.x + threadIdx.x;
    size_t i  = i4 * 4;
    int c = (int)(i & (D_IN - 1));
    float4 xv = *(const float4*)(x + i);
    float4 sc = *(const float4*)(g_scale + c);
    float4 sh = *(const float4*)(g_shift + c);
    float4 t;
    t.x = tanh_fast(fmaf(xv.x, sc.x, sh.x));
    t.y = tanh_fast(fmaf(xv.y, sc.y, sh.y));
    t.z = tanh_fast(fmaf(xv.z, sc.z, sh.z));
    t.w = tanh_fast(fmaf(xv.w, sc.w, sh.w));
    *(float4*)(raw_out + i) = t;
}

// ======================= collapse chain ====================================
__global__ void gemm_nn_split(const float* __restrict__ A,
                              const float* __restrict__ B,
                              float* __restrict__ P,
                              int M, int N, int K, int kchunk) {
    __shared__ float As[16][64];
    __shared__ float Bs[16][65];
    const int tid = threadIdx.x;
    const int tx = tid & 15, ty = tid >> 4;
    const int bn = blockIdx.x * 64, bm = blockIdx.y * 64;
    const int k0 = blockIdx.z * kchunk;

    float acc[4][4];
    #pragma unroll
    for (int i = 0; i < 4; ++i)
        #pragma unroll
        for (int j = 0; j < 4; ++j) acc[i][j] = 0.f;

    for (int kb = k0; kb < k0 + kchunk; kb += 16) {
        #pragma unroll
        for (int t = 0; t < 4; ++t) {
            int idx = tid * 4 + t;
            int r = idx >> 4, kk = idx & 15;
            As[kk][r] = A[(size_t)(bm + r) * K + kb + kk];
        }
        #pragma unroll
        for (int t = 0; t < 4; ++t) {
            int idx = tid + t * 256;
            int c = idx & 63, kk = idx >> 6;
            Bs[kk][c] = B[(size_t)(kb + kk) * N + bn + c];
        }
        __syncthreads();
        #pragma unroll
        for (int kk = 0; kk < 16; ++kk) {
            float a[4], b[4];
            #pragma unroll
            for (int i = 0; i < 4; ++i) a[i] = As[kk][ty * 4 + i];
            #pragma unroll
            for (int j = 0; j < 4; ++j) b[j] = Bs[kk][tx * 4 + j];
            #pragma unroll
            for (int i = 0; i < 4; ++i)
                #pragma unroll
                for (int j = 0; j < 4; ++j)
                    acc[i][j] = fmaf(a[i], b[j], acc[i][j]);
        }
        __syncthreads();
    }
    float* Pb = P + (size_t)blockIdx.z * M * N;
    #pragma unroll
    for (int i = 0; i < 4; ++i)
        #pragma unroll
        for (int j = 0; j < 4; ++j)
            Pb[(size_t)(bm + ty * 4 + i) * N + bn + tx * 4 + j] = acc[i][j];
}

__global__ void reduce_splits(const float* __restrict__ P, float* __restrict__ C,
                              int MN, int S) {
    int i = blockIdx.x * 256 + threadIdx.x;
    if (i >= MN) return;
    float s = 0.f;
    for (int k = 0; k < S; ++k) s += P[(size_t)k * MN + i];
    C[i] = s;
}

__global__ void bias_chain1(const float* __restrict__ W2, const float* __restrict__ b1,
                            const float* __restrict__ b2) {
    int row = blockIdx.x * 8 + (threadIdx.x >> 5);
    int lid = threadIdx.x & 31;
    const float* r = W2 + (size_t)row * F1;
    float s = 0.f;
    #pragma unroll
    for (int k = lid; k < F1; k += 32) s = fmaf(r[k], b1[k], s);
    #pragma unroll
    for (int o = 16; o > 0; o >>= 1) s += __shfl_down_sync(0xFFFFFFFFu, s, o);
    if (lid == 0) g_v1[row] = s + b2[row];
}

__global__ void bias_chain2(const float* __restrict__ Wf, const float* __restrict__ bf) {
    int row = blockIdx.x;
    int t = threadIdx.x;
    const float* r = Wf + (size_t)row * F2;
    float s = 0.f;
    #pragma unroll
    for (int k = t; k < F2; k += 256) s = fmaf(r[k], g_v1[k], s);
    __shared__ float red[256];
    red[t] = s;
    __syncthreads();
    for (int o = 128; o > 0; o >>= 1) {
        if (t < o) red[t] += red[t + o];
        __syncthreads();
    }
    if (t == 0) g_v2[row] = red[0] + bf[row];
}

__global__ void fold_bn() {
    int i = blockIdx.x;
    int t = threadIdx.x;
    float w = g_Weff[i * D_IN + t];
    float wx = w * g_scale[t];
    __nv_bfloat16 hi = __float2bfloat16_rn(wx);
    float lo = wx - __bfloat162float(hi);
    g_Wxh[i * D_IN + t] = hi;
    g_Wxl[i * D_IN + t] = __float2bfloat16_rn(lo);
    __shared__ float red[256];
    red[t] = w * g_shift[t];
    __syncthreads();
    for (int o = 128; o > 0; o >>= 1) {
        if (t < o) red[t] += red[t + o];
        __syncthreads();
    }
    if (t == 0) g_beff[i] = g_v2[i] + red[0];
}

// ======================= fused HMMA main GEMM ==============================
// out = tanh(x @ Wx^T + beff). bf16 x3, K-chunk 32, 2-stage smem pipeline.
#define KCH 32
#define KSTRIDE 40                               // 32 + 8 pad (elems)
#define TILE_B (128 * KSTRIDE * 2)               // 10240 bytes per tile
// stage s base = s*4*TILE_B; within stage: A_HI, A_LO, B_HI, B_LO
#define SMEM_MAIN (8 * TILE_B)                   // 81920

__device__ __forceinline__ unsigned smem_u32(const void* p) {
    unsigned a;
    asm("{ .reg .u64 t; cvta.to.shared.u64 t, %1; cvt.u32.u64 %0, t; }"
        : "=r"(a) : "l"(p));
    return a;
}

__device__ __forceinline__ void ldsm_x4(unsigned r[4], unsigned addr) {
    asm volatile("ldmatrix.sync.aligned.m8n8.x4.shared.b16 {%0,%1,%2,%3}, [%4];"
                 : "=r"(r[0]), "=r"(r[1]), "=r"(r[2]), "=r"(r[3]) : "r"(addr));
}

__device__ __forceinline__ void mma_bf16(float c[4], const unsigned a[4],
                                         unsigned b0, unsigned b1) {
    asm volatile(
        "mma.sync.aligned.m16n8k16.row.col.f32.bf16.bf16.f32 "
        "{%0,%1,%2,%3}, {%4,%5,%6,%7}, {%8,%9}, {%0,%1,%2,%3};"
        : "+f"(c[0]), "+f"(c[1]), "+f"(c[2]), "+f"(c[3])
        : "r"(a[0]), "r"(a[1]), "r"(a[2]), "r"(a[3]), "r"(b0), "r"(b1));
}

__global__ __launch_bounds__(256, 2)
void fused_main(const float* __restrict__ x,
                const __nv_bfloat16* __restrict__ Wxh,
                const __nv_bfloat16* __restrict__ Wxl,
                float* __restrict__ out_main) {
    extern __shared__ __align__(16) char smem[];
    const unsigned sb = smem_u32(smem);
    const int tid = threadIdx.x;
    const int wid = tid >> 5, lane = tid & 31;
    const int warp_m = wid & 3;
    const int warp_n = wid >> 2;
    const int bm = blockIdx.y * 128;
    const int bn = blockIdx.x * 128;

    const int arow = tid >> 1;               // 0..127
    const int acol = (tid & 1) * 16;         // 0 or 16

    float acc[2][8][4];
    #pragma unroll
    for (int m = 0; m < 2; ++m)
        #pragma unroll
        for (int n = 0; n < 8; ++n)
            #pragma unroll
            for (int q = 0; q < 4; ++q) acc[m][n][q] = 0.f;

    // ---- helpers as lambdas ----
    auto convert_store_A = [&](const float4 av[4], int stage) {
        char* base = smem + stage * 4 * TILE_B;       // A_HI
        char* basl = base + TILE_B;                   // A_LO
        #pragma unroll
        for (int j = 0; j < 4; ++j) {
            float4 v = av[j];
            __nv_bfloat162 h01 = __floats2bfloat162_rn(v.x, v.y);
            __nv_bfloat162 h23 = __floats2bfloat162_rn(v.z, v.w);
            float l0 = v.x - __bfloat162float(h01.x);
            float l1 = v.y - __bfloat162float(h01.y);
            float l2 = v.z - __bfloat162float(h23.x);
            float l3 = v.w - __bfloat162float(h23.y);
            __nv_bfloat162 lo01 = __floats2bfloat162_rn(l0, l1);
            __nv_bfloat162 lo23 = __floats2bfloat162_rn(l2, l3);
            unsigned boff = (unsigned)((arow * KSTRIDE + acol + j * 4) * 2);
            *(unsigned*)(base + boff)     = *(unsigned*)&h01;
            *(unsigned*)(base + boff + 4) = *(unsigned*)&h23;
            *(unsigned*)(basl + boff)     = *(unsigned*)&lo01;
            *(unsigned*)(basl + boff + 4) = *(unsigned*)&lo23;
        }
    };
    auto load_store_B = [&](int kc, int stage) {
        char* bh = smem + stage * 4 * TILE_B + 2 * TILE_B;
        char* bl = bh + TILE_B;
        const size_t wb = (size_t)(bn + arow) * D_IN + kc + acol;
        #pragma unroll
        for (int j = 0; j < 2; ++j) {
            unsigned boff = (unsigned)((arow * KSTRIDE + acol + j * 8) * 2);
            *(uint4*)(bh + boff) = *(const uint4*)(Wxh + wb + j * 8);
            *(uint4*)(bl + boff) = *(const uint4*)(Wxl + wb + j * 8);
        }
    };
    auto mma_stage = [&](int stage) {
        unsigned abase = sb + stage * 4 * TILE_B;
        unsigned bbase = abase + 2 * TILE_B;
        #pragma unroll
        for (int ks = 0; ks < 2; ++ks) {
            const int col = ks * 16 + (lane >> 4) * 8;
            unsigned ah[2][4], al[2][4];
            #pragma unroll
            for (int m = 0; m < 2; ++m) {
                int row = warp_m * 32 + m * 16 + (lane & 15);
                unsigned off = (unsigned)((row * KSTRIDE + col) * 2);
                ldsm_x4(ah[m], abase + off);
                ldsm_x4(al[m], abase + TILE_B + off);
            }
            #pragma unroll
            for (int g = 0; g < 4; ++g) {
                int nrow = warp_n * 64 + g * 16 + (lane & 15);
                unsigned off = (unsigned)((nrow * KSTRIDE + col) * 2);
                unsigned bhf[4], blf[4];
                ldsm_x4(bhf, bbase + off);
                ldsm_x4(blf, bbase + TILE_B + off);
                #pragma unroll
                for (int m = 0; m < 2; ++m) {
                    #pragma unroll
                    for (int s = 0; s < 2; ++s) {
                        float* a = acc[m][g * 2 + s];
                        mma_bf16(a, ah[m], bhf[s], bhf[s + 2]);
                        mma_bf16(a, ah[m], blf[s], blf[s + 2]);
                        mma_bf16(a, al[m], bhf[s], bhf[s + 2]);
                    }
                }
            }
        }
    };

    // ---- prologue: chunk 0 into stage 0 ----
    {
        float4 av[4];
        const float* xp = x + (size_t)(bm + arow) * D_IN + acol;
        #pragma unroll
        for (int j = 0; j < 4; ++j) av[j] = *(const float4*)(xp + j * 4);
        convert_store_A(av, 0);
        load_store_B(0, 0);
    }
    __syncthreads();

    // ---- pipelined main loop: 8 chunks of K=32 ----
    #pragma unroll 1
    for (int c = 0; c < 8; ++c) {
        float4 av[4];
        if (c < 7) {
            const float* xp = x + (size_t)(bm + arow) * D_IN + (c + 1) * KCH + acol;
            #pragma unroll
            for (int j = 0; j < 4; ++j) av[j] = *(const float4*)(xp + j * 4);
        }
        mma_stage(c & 1);
        if (c < 7) {
            convert_store_A(av, (c + 1) & 1);
            load_store_B((c + 1) * KCH, (c + 1) & 1);
        }
        __syncthreads();
    }

    // ---- epilogue: bias + tanh.approx + store ----
    const int gr = lane >> 2;
    const int gc = (lane & 3) * 2;
    #pragma unroll
    for (int m = 0; m < 2; ++m) {
        #pragma unroll
        for (int n = 0; n < 8; ++n) {
            int col = bn + warp_n * 64 + n * 8 + gc;
            float2 bv = *(const float2*)(g_beff + col);
            int r0 = bm + warp_m * 32 + m * 16 + gr;
            float2 o0, o1;
            o0.x = tanh_fast(acc[m][n][0] + bv.x);
            o0.y = tanh_fast(acc[m][n][1] + bv.y);
            o1.x = tanh_fast(acc[m][n][2] + bv.x);
            o1.y = tanh_fast(acc[m][n][3] + bv.y);
            *(float2*)(out_main + (size_t)r0 * D_IN + col)       = o0;
            *(float2*)(out_main + (size_t)(r0 + 8) * D_IN + col) = o1;
        }
    }
}

// ======================= launch ============================================
extern "C" void kernel_launch(void* const* d_in, const int* in_sizes, int n_in,
                              void* d_out, int out_size) {
    const float* x     = (const float*)d_in[0];
    const float* gamma = (const float*)d_in[1];
    const float* beta  = (const float*)d_in[2];
    const float* W1    = (const float*)d_in[3];
    const float* b1    = (const float*)d_in[4];
    const float* W2    = (const float*)d_in[5];
    const float* b2    = (const float*)d_in[6];
    const float* Wf    = (const float*)d_in[7];
    const float* bf    = (const float*)d_in[8];

    float* out_main = (float*)d_out;
    float* out_raw  = (float*)d_out + (size_t)N_ROWS * D_IN;

    float *part0, *T0, *part1, *Weff;
    __nv_bfloat16 *Wxh, *Wxl;
    cudaGetSymbolAddress((void**)&part0, g_part0);
    cudaGetSymbolAddress((void**)&T0,    g_T0);
    cudaGetSymbolAddress((void**)&part1, g_part1);
    cudaGetSymbolAddress((void**)&Weff,  g_Weff);
    cudaGetSymbolAddress((void**)&Wxh,   g_Wxh);
    cudaGetSymbolAddress((void**)&Wxl,   g_Wxl);

    static cudaStream_t sBN = nullptr, sBias = nullptr;
    static cudaEvent_t evFork = nullptr, evBN = nullptr, evBias = nullptr;
    static int init_done = 0;
    if (!init_done) {
        cudaFuncSetAttribute(fused_main, cudaFuncAttributeMaxDynamicSharedMemorySize,
                             SMEM_MAIN);
        cudaStreamCreateWithFlags(&sBN,   cudaStreamNonBlocking);
        cudaStreamCreateWithFlags(&sBias, cudaStreamNonBlocking);
        cudaEventCreateWithFlags(&evFork, cudaEventDisableTiming);
        cudaEventCreateWithFlags(&evBN,   cudaEventDisableTiming);
        cudaEventCreateWithFlags(&evBias, cudaEventDisableTiming);
        init_done = 1;
    }

    // ---- fork
    cudaEventRecord(evFork, 0);
    cudaStreamWaitEvent(sBN,   evFork, 0);
    cudaStreamWaitEvent(sBias, evFork, 0);

    // branch BN (stream sBN): stats then raw_feats (overlaps collapse)
    bn_zero<<<1, 256, 0, sBN>>>();
    bn_reduce<<<256, 256, 0, sBN>>>(x);
    bn_finalize<<<1, 256, 0, sBN>>>(gamma, beta);
    bn_raw<<<(N_ROWS * D_IN / 4) / 256, 256, 0, sBN>>>(x, out_raw);
    cudaEventRecord(evBN, sBN);

    // branch bias (stream sBias)
    bias_chain1<<<F2 / 8, 256, 0, sBias>>>(W2, b1, b2);
    bias_chain2<<<D_IN, 256, 0, sBias>>>(Wf, bf);
    cudaEventRecord(evBias, sBias);

    // branch weight collapse (default stream): Weff = Wf @ W2 @ W1
    gemm_nn_split<<<dim3(512 / 64, 256 / 64, 16), 256>>>(Wf, W2, part0, 256, 512, 2048, 128);
    reduce_splits<<<(256 * 512) / 256, 256>>>(part0, T0, 256 * 512, 16);
    gemm_nn_split<<<dim3(256 / 64, 256 / 64, 16), 256>>>(T0, W1, part1, 256, 256, 512, 32);
    reduce_splits<<<(256 * 256) / 256, 256>>>(part1, Weff, 256 * 256, 16);

    // ---- join
    cudaStreamWaitEvent(0, evBN, 0);
    cudaStreamWaitEvent(0, evBias, 0);

    fold_bn<<<256, 256>>>();

    fused_main<<<dim3(2, N_ROWS / 128), 256, SMEM_MAIN>>>(x, Wxh, Wxl, out_main);
}

// round 7
// speedup vs baseline: 27.7838x; 1.0234x over previous
#include <cuda_runtime.h>
#include <cuda_bf16.h>
#include <cuda_fp16.h>
#include <math.h>

#define N_ROWS 65536
#define D_IN   256
#define F1     512
#define F2     2048
#define EPS    1e-5f

// ======================= scratch (device globals) ===========================
__device__ float g_bnpart[2 * 256 * 256];        // per-block BN partials
__device__ __align__(16) float g_scale[D_IN];
__device__ __align__(16) float g_shift[D_IN];
__device__ float g_part0[16 * 256 * 512];
__device__ float g_T0[256 * 512];
__device__ float g_part1[16 * 256 * 256];
__device__ __align__(16) __half g_Wxh[256 * 256];
__device__ __align__(16) __half g_Wxl[256 * 256];
__device__ float g_v1[F2];
__device__ float g_v2[D_IN];
__device__ __align__(16) float g_beff[D_IN];

__device__ __forceinline__ float tanh_fast(float v) {
    float r;
    asm("tanh.approx.f32 %0, %1;" : "=f"(r) : "f"(v));
    return r;
}

// ======================= BN stats (deterministic, no atomics) ==============
__global__ void bn_reduce(const float* __restrict__ x) {
    const int col = threadIdx.x;
    const int b = blockIdx.x;                 // 256 blocks, 256 rows each
    size_t base = (size_t)b * 256 * D_IN + col;
    float s = 0.f, sq = 0.f;
    #pragma unroll 8
    for (int r = 0; r < 256; ++r) {
        float v = x[base + (size_t)r * D_IN];
        s += v; sq += v * v;
    }
    g_bnpart[b * 256 + col]           = s;
    g_bnpart[65536 + b * 256 + col]   = sq;
}

__global__ void bn_finalize(const float* __restrict__ gamma,
                            const float* __restrict__ beta) {
    int j = threadIdx.x;
    float s = 0.f, sq = 0.f;
    #pragma unroll 4
    for (int b = 0; b < 256; ++b) {
        s  += g_bnpart[b * 256 + j];
        sq += g_bnpart[65536 + b * 256 + j];
    }
    float inv_n = 1.0f / (float)N_ROWS;
    float mu  = s * inv_n;
    float var = sq * inv_n - mu * mu;
    float sc  = gamma[j] * rsqrtf(var + EPS);
    g_scale[j] = sc;
    g_shift[j] = beta[j] - mu * sc;
}

// raw_feats = tanh(x*scale + shift)
__global__ void bn_raw(const float* __restrict__ x, float* __restrict__ raw_out) {
    size_t i4 = (size_t)blockIdx.x * blockDim.x + threadIdx.x;
    size_t i  = i4 * 4;
    int c = (int)(i & (D_IN - 1));
    float4 xv = *(const float4*)(x + i);
    float4 sc = *(const float4*)(g_scale + c);
    float4 sh = *(const float4*)(g_shift + c);
    float4 t;
    t.x = tanh_fast(fmaf(xv.x, sc.x, sh.x));
    t.y = tanh_fast(fmaf(xv.y, sc.y, sh.y));
    t.z = tanh_fast(fmaf(xv.z, sc.z, sh.z));
    t.w = tanh_fast(fmaf(xv.w, sc.w, sh.w));
    *(float4*)(raw_out + i) = t;
}

// ======================= collapse chain ====================================
__global__ void gemm_nn_split(const float* __restrict__ A,
                              const float* __restrict__ B,
                              float* __restrict__ P,
                              int M, int N, int K, int kchunk) {
    __shared__ float As[16][64];
    __shared__ float Bs[16][65];
    const int tid = threadIdx.x;
    const int tx = tid & 15, ty = tid >> 4;
    const int bn = blockIdx.x * 64, bm = blockIdx.y * 64;
    const int k0 = blockIdx.z * kchunk;

    float acc[4][4];
    #pragma unroll
    for (int i = 0; i < 4; ++i)
        #pragma unroll
        for (int j = 0; j < 4; ++j) acc[i][j] = 0.f;

    for (int kb = k0; kb < k0 + kchunk; kb += 16) {
        #pragma unroll
        for (int t = 0; t < 4; ++t) {
            int idx = tid * 4 + t;
            int r = idx >> 4, kk = idx & 15;
            As[kk][r] = A[(size_t)(bm + r) * K + kb + kk];
        }
        #pragma unroll
        for (int t = 0; t < 4; ++t) {
            int idx = tid + t * 256;
            int c = idx & 63, kk = idx >> 6;
            Bs[kk][c] = B[(size_t)(kb + kk) * N + bn + c];
        }
        __syncthreads();
        #pragma unroll
        for (int kk = 0; kk < 16; ++kk) {
            float a[4], b[4];
            #pragma unroll
            for (int i = 0; i < 4; ++i) a[i] = As[kk][ty * 4 + i];
            #pragma unroll
            for (int j = 0; j < 4; ++j) b[j] = Bs[kk][tx * 4 + j];
            #pragma unroll
            for (int i = 0; i < 4; ++i)
                #pragma unroll
                for (int j = 0; j < 4; ++j)
                    acc[i][j] = fmaf(a[i], b[j], acc[i][j]);
        }
        __syncthreads();
    }
    float* Pb = P + (size_t)blockIdx.z * M * N;
    #pragma unroll
    for (int i = 0; i < 4; ++i)
        #pragma unroll
        for (int j = 0; j < 4; ++j)
            Pb[(size_t)(bm + ty * 4 + i) * N + bn + tx * 4 + j] = acc[i][j];
}

__global__ void reduce_splits(const float* __restrict__ P, float* __restrict__ C,
                              int MN, int S) {
    int i = blockIdx.x * 256 + threadIdx.x;
    if (i >= MN) return;
    float s = 0.f;
    for (int k = 0; k < S; ++k) s += P[(size_t)k * MN + i];
    C[i] = s;
}

__global__ void bias_chain1(const float* __restrict__ W2, const float* __restrict__ b1,
                            const float* __restrict__ b2) {
    int row = blockIdx.x * 8 + (threadIdx.x >> 5);
    int lid = threadIdx.x & 31;
    const float* r = W2 + (size_t)row * F1;
    float s = 0.f;
    #pragma unroll
    for (int k = lid; k < F1; k += 32) s = fmaf(r[k], b1[k], s);
    #pragma unroll
    for (int o = 16; o > 0; o >>= 1) s += __shfl_down_sync(0xFFFFFFFFu, s, o);
    if (lid == 0) g_v1[row] = s + b2[row];
}

__global__ void bias_chain2(const float* __restrict__ Wf, const float* __restrict__ bf) {
    int row = blockIdx.x;
    int t = threadIdx.x;
    const float* r = Wf + (size_t)row * F2;
    float s = 0.f;
    #pragma unroll
    for (int k = t; k < F2; k += 256) s = fmaf(r[k], g_v1[k], s);
    __shared__ float red[256];
    red[t] = s;
    __syncthreads();
    for (int o = 128; o > 0; o >>= 1) {
        if (t < o) red[t] += red[t + o];
        __syncthreads();
    }
    if (t == 0) g_v2[row] = red[0] + bf[row];
}

// sums part1 splits, folds BN scale, splits weights to fp16 hi/lo, builds beff
__global__ void fold_bn() {
    int i = blockIdx.x;
    int t = threadIdx.x;
    float w = 0.f;
    #pragma unroll
    for (int s = 0; s < 16; ++s)
        w += g_part1[s * 65536 + i * D_IN + t];
    float wx = w * g_scale[t];
    __half hi = __float2half_rn(wx);
    float lo = wx - __half2float(hi);
    g_Wxh[i * D_IN + t] = hi;
    g_Wxl[i * D_IN + t] = __float2half_rn(lo);
    __shared__ float red[256];
    red[t] = w * g_shift[t];
    __syncthreads();
    for (int o = 128; o > 0; o >>= 1) {
        if (t < o) red[t] += red[t + o];
        __syncthreads();
    }
    if (t == 0) g_beff[i] = g_v2[i] + red[0];
}

// ======================= fused HMMA main GEMM (fp16 x2) ====================
// out = tanh(x @ Wx^T + beff). x single fp16, W split hi/lo. 2 mma per step.
#define KCH 32
#define KSTRIDE 40
#define TILE_B (128 * KSTRIDE * 2)       // 10240 B
// stage layout: A | B_HI | B_LO  (3 tiles); stage s at s*3*TILE_B
#define SMEM_MAIN (6 * TILE_B)           // 61440 B

__device__ __forceinline__ unsigned smem_u32(const void* p) {
    unsigned a;
    asm("{ .reg .u64 t; cvta.to.shared.u64 t, %1; cvt.u32.u64 %0, t; }"
        : "=r"(a) : "l"(p));
    return a;
}

__device__ __forceinline__ void ldsm_x4(unsigned r[4], unsigned addr) {
    asm volatile("ldmatrix.sync.aligned.m8n8.x4.shared.b16 {%0,%1,%2,%3}, [%4];"
                 : "=r"(r[0]), "=r"(r[1]), "=r"(r[2]), "=r"(r[3]) : "r"(addr));
}

__device__ __forceinline__ void mma_fp16(float c[4], const unsigned a[4],
                                         unsigned b0, unsigned b1) {
    asm volatile(
        "mma.sync.aligned.m16n8k16.row.col.f32.f16.f16.f32 "
        "{%0,%1,%2,%3}, {%4,%5,%6,%7}, {%8,%9}, {%0,%1,%2,%3};"
        : "+f"(c[0]), "+f"(c[1]), "+f"(c[2]), "+f"(c[3])
        : "r"(a[0]), "r"(a[1]), "r"(a[2]), "r"(a[3]), "r"(b0), "r"(b1));
}

__global__ __launch_bounds__(256, 2)
void fused_main(const float* __restrict__ x,
                const __half* __restrict__ Wxh,
                const __half* __restrict__ Wxl,
                float* __restrict__ out_main) {
    extern __shared__ __align__(16) char smem[];
    const unsigned sb = smem_u32(smem);
    const int tid = threadIdx.x;
    const int wid = tid >> 5, lane = tid & 31;
    const int warp_m = wid & 3;
    const int warp_n = wid >> 2;
    const int bm = blockIdx.y * 128;
    const int bn = blockIdx.x * 128;

    const int arow = tid >> 1;               // 0..127
    const int acol = (tid & 1) * 16;         // 0 or 16

    float acc[2][8][4];
    #pragma unroll
    for (int m = 0; m < 2; ++m)
        #pragma unroll
        for (int n = 0; n < 8; ++n)
            #pragma unroll
            for (int q = 0; q < 4; ++q) acc[m][n][q] = 0.f;

    auto convert_store_A = [&](const float4 av[4], int stage) {
        char* base = smem + stage * 3 * TILE_B;
        #pragma unroll
        for (int p = 0; p < 2; ++p) {              // two uint4 stores
            __half2 h0 = __floats2half2_rn(av[p*2].x,   av[p*2].y);
            __half2 h1 = __floats2half2_rn(av[p*2].z,   av[p*2].w);
            __half2 h2 = __floats2half2_rn(av[p*2+1].x, av[p*2+1].y);
            __half2 h3 = __floats2half2_rn(av[p*2+1].z, av[p*2+1].w);
            uint4 pk;
            pk.x = *(unsigned*)&h0; pk.y = *(unsigned*)&h1;
            pk.z = *(unsigned*)&h2; pk.w = *(unsigned*)&h3;
            unsigned boff = (unsigned)((arow * KSTRIDE + acol + p * 8) * 2);
            *(uint4*)(base + boff) = pk;
        }
    };
    auto load_store_B = [&](int kc, int stage) {
        char* bh = smem + stage * 3 * TILE_B + TILE_B;
        char* bl = bh + TILE_B;
        const size_t wb = (size_t)(bn + arow) * D_IN + kc + acol;
        #pragma unroll
        for (int j = 0; j < 2; ++j) {
            unsigned boff = (unsigned)((arow * KSTRIDE + acol + j * 8) * 2);
            *(uint4*)(bh + boff) = *(const uint4*)(Wxh + wb + j * 8);
            *(uint4*)(bl + boff) = *(const uint4*)(Wxl + wb + j * 8);
        }
    };
    auto mma_stage = [&](int stage) {
        unsigned abase = sb + stage * 3 * TILE_B;
        unsigned bbase = abase + TILE_B;
        #pragma unroll
        for (int ks = 0; ks < 2; ++ks) {
            const int col = ks * 16 + (lane >> 4) * 8;
            unsigned ah[2][4];
            #pragma unroll
            for (int m = 0; m < 2; ++m) {
                int row = warp_m * 32 + m * 16 + (lane & 15);
                unsigned off = (unsigned)((row * KSTRIDE + col) * 2);
                ldsm_x4(ah[m], abase + off);
            }
            #pragma unroll
            for (int g = 0; g < 4; ++g) {
                int nrow = warp_n * 64 + g * 16 + (lane & 15);
                unsigned off = (unsigned)((nrow * KSTRIDE + col) * 2);
                unsigned bhf[4], blf[4];
                ldsm_x4(bhf, bbase + off);
                ldsm_x4(blf, bbase + TILE_B + off);
                #pragma unroll
                for (int m = 0; m < 2; ++m) {
                    #pragma unroll
                    for (int s = 0; s < 2; ++s) {
                        float* a = acc[m][g * 2 + s];
                        mma_fp16(a, ah[m], bhf[s], bhf[s + 2]);
                        mma_fp16(a, ah[m], blf[s], blf[s + 2]);
                    }
                }
            }
        }
    };

    // prologue
    {
        float4 av[4];
        const float* xp = x + (size_t)(bm + arow) * D_IN + acol;
        #pragma unroll
        for (int j = 0; j < 4; ++j) av[j] = *(const float4*)(xp + j * 4);
        convert_store_A(av, 0);
        load_store_B(0, 0);
    }
    __syncthreads();

    #pragma unroll 1
    for (int c = 0; c < 8; ++c) {
        float4 av[4];
        if (c < 7) {
            const float* xp = x + (size_t)(bm + arow) * D_IN + (c + 1) * KCH + acol;
            #pragma unroll
            for (int j = 0; j < 4; ++j) av[j] = *(const float4*)(xp + j * 4);
        }
        mma_stage(c & 1);
        if (c < 7) {
            convert_store_A(av, (c + 1) & 1);
            load_store_B((c + 1) * KCH, (c + 1) & 1);
        }
        __syncthreads();
    }

    // epilogue
    const int gr = lane >> 2;
    const int gc = (lane & 3) * 2;
    #pragma unroll
    for (int m = 0; m < 2; ++m) {
        #pragma unroll
        for (int n = 0; n < 8; ++n) {
            int col = bn + warp_n * 64 + n * 8 + gc;
            float2 bv = *(const float2*)(g_beff + col);
            int r0 = bm + warp_m * 32 + m * 16 + gr;
            float2 o0, o1;
            o0.x = tanh_fast(acc[m][n][0] + bv.x);
            o0.y = tanh_fast(acc[m][n][1] + bv.y);
            o1.x = tanh_fast(acc[m][n][2] + bv.x);
            o1.y = tanh_fast(acc[m][n][3] + bv.y);
            *(float2*)(out_main + (size_t)r0 * D_IN + col)       = o0;
            *(float2*)(out_main + (size_t)(r0 + 8) * D_IN + col) = o1;
        }
    }
}

// ======================= launch ============================================
extern "C" void kernel_launch(void* const* d_in, const int* in_sizes, int n_in,
                              void* d_out, int out_size) {
    const float* x     = (const float*)d_in[0];
    const float* gamma = (const float*)d_in[1];
    const float* beta  = (const float*)d_in[2];
    const float* W1    = (const float*)d_in[3];
    const float* b1    = (const float*)d_in[4];
    const float* W2    = (const float*)d_in[5];
    const float* b2    = (const float*)d_in[6];
    const float* Wf    = (const float*)d_in[7];
    const float* bf    = (const float*)d_in[8];

    float* out_main = (float*)d_out;
    float* out_raw  = (float*)d_out + (size_t)N_ROWS * D_IN;

    float *part0, *T0, *part1;
    __half *Wxh, *Wxl;
    cudaGetSymbolAddress((void**)&part0, g_part0);
    cudaGetSymbolAddress((void**)&T0,    g_T0);
    cudaGetSymbolAddress((void**)&part1, g_part1);
    cudaGetSymbolAddress((void**)&Wxh,   g_Wxh);
    cudaGetSymbolAddress((void**)&Wxl,   g_Wxl);

    static cudaStream_t sBN = nullptr, sBias = nullptr;
    static cudaEvent_t evFork = nullptr, evBN = nullptr, evBias = nullptr;
    static int init_done = 0;
    if (!init_done) {
        cudaFuncSetAttribute(fused_main, cudaFuncAttributeMaxDynamicSharedMemorySize,
                             SMEM_MAIN);
        cudaStreamCreateWithFlags(&sBN,   cudaStreamNonBlocking);
        cudaStreamCreateWithFlags(&sBias, cudaStreamNonBlocking);
        cudaEventCreateWithFlags(&evFork, cudaEventDisableTiming);
        cudaEventCreateWithFlags(&evBN,   cudaEventDisableTiming);
        cudaEventCreateWithFlags(&evBias, cudaEventDisableTiming);
        init_done = 1;
    }

    // fork
    cudaEventRecord(evFork, 0);
    cudaStreamWaitEvent(sBN,   evFork, 0);
    cudaStreamWaitEvent(sBias, evFork, 0);

    // BN branch
    bn_reduce<<<256, 256, 0, sBN>>>(x);
    bn_finalize<<<1, 256, 0, sBN>>>(gamma, beta);
    bn_raw<<<(N_ROWS * D_IN / 4) / 256, 256, 0, sBN>>>(x, out_raw);
    cudaEventRecord(evBN, sBN);

    // bias branch
    bias_chain1<<<F2 / 8, 256, 0, sBias>>>(W2, b1, b2);
    bias_chain2<<<D_IN, 256, 0, sBias>>>(Wf, bf);
    cudaEventRecord(evBias, sBias);

    // weight collapse branch (default stream)
    gemm_nn_split<<<dim3(512 / 64, 256 / 64, 16), 256>>>(Wf, W2, part0, 256, 512, 2048, 128);
    reduce_splits<<<(256 * 512) / 256, 256>>>(part0, T0, 256 * 512, 16);
    gemm_nn_split<<<dim3(256 / 64, 256 / 64, 16), 256>>>(T0, W1, part1, 256, 256, 512, 32);

    // join
    cudaStreamWaitEvent(0, evBN, 0);
    cudaStreamWaitEvent(0, evBias, 0);

    fold_bn<<<256, 256>>>();   // also reduces part1 splits

    fused_main<<<dim3(2, N_ROWS / 128), 256, SMEM_MAIN>>>(x, Wxh, Wxl, out_main);
}

// round 9
// speedup vs baseline: 28.2805x; 1.0179x over previous
#include <cuda_runtime.h>
#include <cuda_bf16.h>
#include <cuda_fp16.h>
#include <math.h>

#define N_ROWS 65536
#define D_IN   256
#define F1     512
#define F2     2048
#define EPS    1e-5f

// ======================= scratch (device globals) ===========================
__device__ float g_bnpart[2 * 256 * 256];
__device__ __align__(16) float g_scale[D_IN];
__device__ __align__(16) float g_shift[D_IN];
__device__ float g_part0[16 * 256 * 512];
__device__ float g_T0[256 * 512];
__device__ float g_part1[16 * 256 * 256];
__device__ __align__(16) __half g_Wxh[256 * 256];
__device__ __align__(16) __half g_Wxl[256 * 256];
__device__ __align__(16) __half g_xh[(size_t)N_ROWS * D_IN];   // x as fp16 (32 MB)
__device__ float g_v1[F2];
__device__ float g_v2[D_IN];
__device__ __align__(16) float g_beff[D_IN];

__device__ __forceinline__ float tanh_fast(float v) {
    float r;
    asm("tanh.approx.f32 %0, %1;" : "=f"(r) : "f"(v));
    return r;
}

// ======================= x -> fp16 (independent of BN stats) ================
__global__ void x2half(const float* __restrict__ x, __half* __restrict__ xh) {
    size_t i8 = (size_t)blockIdx.x * blockDim.x + threadIdx.x;
    size_t i  = i8 * 8;
    float4 a = *(const float4*)(x + i);
    float4 b = *(const float4*)(x + i + 4);
    __half2 h0 = __floats2half2_rn(a.x, a.y);
    __half2 h1 = __floats2half2_rn(a.z, a.w);
    __half2 h2 = __floats2half2_rn(b.x, b.y);
    __half2 h3 = __floats2half2_rn(b.z, b.w);
    uint4 pk;
    pk.x = *(unsigned*)&h0; pk.y = *(unsigned*)&h1;
    pk.z = *(unsigned*)&h2; pk.w = *(unsigned*)&h3;
    *(uint4*)(xh + i) = pk;
}

// ======================= BN stats (deterministic) ==========================
__global__ void bn_reduce(const float* __restrict__ x) {
    const int col = threadIdx.x;
    const int b = blockIdx.x;
    size_t base = (size_t)b * 256 * D_IN + col;
    float s = 0.f, sq = 0.f;
    #pragma unroll 8
    for (int r = 0; r < 256; ++r) {
        float v = x[base + (size_t)r * D_IN];
        s += v; sq += v * v;
    }
    g_bnpart[b * 256 + col]         = s;
    g_bnpart[65536 + b * 256 + col] = sq;
}

__global__ void bn_finalize(const float* __restrict__ gamma,
                            const float* __restrict__ beta) {
    int j = threadIdx.x;
    float s = 0.f, sq = 0.f;
    #pragma unroll 4
    for (int b = 0; b < 256; ++b) {
        s  += g_bnpart[b * 256 + j];
        sq += g_bnpart[65536 + b * 256 + j];
    }
    float inv_n = 1.0f / (float)N_ROWS;
    float mu  = s * inv_n;
    float var = sq * inv_n - mu * mu;
    float sc  = gamma[j] * rsqrtf(var + EPS);
    g_scale[j] = sc;
    g_shift[j] = beta[j] - mu * sc;
}

__global__ void bn_raw(const float* __restrict__ x, float* __restrict__ raw_out) {
    size_t i4 = (size_t)blockIdx.x * blockDim.x + threadIdx.x;
    size_t i  = i4 * 4;
    int c = (int)(i & (D_IN - 1));
    float4 xv = *(const float4*)(x + i);
    float4 sc = *(const float4*)(g_scale + c);
    float4 sh = *(const float4*)(g_shift + c);
    float4 t;
    t.x = tanh_fast(fmaf(xv.x, sc.x, sh.x));
    t.y = tanh_fast(fmaf(xv.y, sc.y, sh.y));
    t.z = tanh_fast(fmaf(xv.z, sc.z, sh.z));
    t.w = tanh_fast(fmaf(xv.w, sc.w, sh.w));
    *(float4*)(raw_out + i) = t;
}

// ======================= collapse chain ====================================
__global__ void gemm_nn_split(const float* __restrict__ A,
                              const float* __restrict__ B,
                              float* __restrict__ P,
                              int M, int N, int K, int kchunk) {
    __shared__ float As[16][64];
    __shared__ float Bs[16][65];
    const int tid = threadIdx.x;
    const int tx = tid & 15, ty = tid >> 4;
    const int bn = blockIdx.x * 64, bm = blockIdx.y * 64;
    const int k0 = blockIdx.z * kchunk;

    float acc[4][4];
    #pragma unroll
    for (int i = 0; i < 4; ++i)
        #pragma unroll
        for (int j = 0; j < 4; ++j) acc[i][j] = 0.f;

    for (int kb = k0; kb < k0 + kchunk; kb += 16) {
        #pragma unroll
        for (int t = 0; t < 4; ++t) {
            int idx = tid * 4 + t;
            int r = idx >> 4, kk = idx & 15;
            As[kk][r] = A[(size_t)(bm + r) * K + kb + kk];
        }
        #pragma unroll
        for (int t = 0; t < 4; ++t) {
            int idx = tid + t * 256;
            int c = idx & 63, kk = idx >> 6;
            Bs[kk][c] = B[(size_t)(kb + kk) * N + bn + c];
        }
        __syncthreads();
        #pragma unroll
        for (int kk = 0; kk < 16; ++kk) {
            float a[4], b[4];
            #pragma unroll
            for (int i = 0; i < 4; ++i) a[i] = As[kk][ty * 4 + i];
            #pragma unroll
            for (int j = 0; j < 4; ++j) b[j] = Bs[kk][tx * 4 + j];
            #pragma unroll
            for (int i = 0; i < 4; ++i)
                #pragma unroll
                for (int j = 0; j < 4; ++j)
                    acc[i][j] = fmaf(a[i], b[j], acc[i][j]);
        }
        __syncthreads();
    }
    float* Pb = P + (size_t)blockIdx.z * M * N;
    #pragma unroll
    for (int i = 0; i < 4; ++i)
        #pragma unroll
        for (int j = 0; j < 4; ++j)
            Pb[(size_t)(bm + ty * 4 + i) * N + bn + tx * 4 + j] = acc[i][j];
}

__global__ void reduce_splits(const float* __restrict__ P, float* __restrict__ C,
                              int MN, int S) {
    int i = blockIdx.x * 256 + threadIdx.x;
    if (i >= MN) return;
    float s = 0.f;
    for (int k = 0; k < S; ++k) s += P[(size_t)k * MN + i];
    C[i] = s;
}

__global__ void bias_chain1(const float* __restrict__ W2, const float* __restrict__ b1,
                            const float* __restrict__ b2) {
    int row = blockIdx.x * 8 + (threadIdx.x >> 5);
    int lid = threadIdx.x & 31;
    const float* r = W2 + (size_t)row * F1;
    float s = 0.f;
    #pragma unroll
    for (int k = lid; k < F1; k += 32) s = fmaf(r[k], b1[k], s);
    #pragma unroll
    for (int o = 16; o > 0; o >>= 1) s += __shfl_down_sync(0xFFFFFFFFu, s, o);
    if (lid == 0) g_v1[row] = s + b2[row];
}

__global__ void bias_chain2(const float* __restrict__ Wf, const float* __restrict__ bf) {
    int row = blockIdx.x;
    int t = threadIdx.x;
    const float* r = Wf + (size_t)row * F2;
    float s = 0.f;
    #pragma unroll
    for (int k = t; k < F2; k += 256) s = fmaf(r[k], g_v1[k], s);
    __shared__ float red[256];
    red[t] = s;
    __syncthreads();
    for (int o = 128; o > 0; o >>= 1) {
        if (t < o) red[t] += red[t + o];
        __syncthreads();
    }
    if (t == 0) g_v2[row] = red[0] + bf[row];
}

__global__ void fold_bn() {
    int i = blockIdx.x;
    int t = threadIdx.x;
    float w = 0.f;
    #pragma unroll
    for (int s = 0; s < 16; ++s)
        w += g_part1[s * 65536 + i * D_IN + t];
    float wx = w * g_scale[t];
    __half hi = __float2half_rn(wx);
    float lo = wx - __half2float(hi);
    g_Wxh[i * D_IN + t] = hi;
    g_Wxl[i * D_IN + t] = __float2half_rn(lo);
    __shared__ float red[256];
    red[t] = w * g_shift[t];
    __syncthreads();
    for (int o = 128; o > 0; o >>= 1) {
        if (t < o) red[t] += red[t + o];
        __syncthreads();
    }
    if (t == 0) g_beff[i] = g_v2[i] + red[0];
}

// ======================= fused HMMA main GEMM (fp16 x2) ====================
// A (x fp16) loaded to smem ONCE; B (W hi/lo) double-buffered in K chunks.
#define KCH 32
#define KSA 264                            // A row stride: 256 + 8 pad (elems)
#define A_BYTES (128 * KSA * 2)            // 67584
#define KSB 40                             // B chunk row stride (elems)
#define B_TILE (128 * KSB * 2)             // 10240
#define B_OFF A_BYTES
#define SMEM_MAIN (A_BYTES + 4 * B_TILE)   // 108544

__device__ __forceinline__ unsigned smem_u32(const void* p) {
    unsigned a;
    asm("{ .reg .u64 t; cvta.to.shared.u64 t, %1; cvt.u32.u64 %0, t; }"
        : "=r"(a) : "l"(p));
    return a;
}

__device__ __forceinline__ void ldsm_x4(unsigned r[4], unsigned addr) {
    asm volatile("ldmatrix.sync.aligned.m8n8.x4.shared.b16 {%0,%1,%2,%3}, [%4];"
                 : "=r"(r[0]), "=r"(r[1]), "=r"(r[2]), "=r"(r[3]) : "r"(addr));
}

__device__ __forceinline__ void mma_fp16(float c[4], const unsigned a[4],
                                         unsigned b0, unsigned b1) {
    asm volatile(
        "mma.sync.aligned.m16n8k16.row.col.f32.f16.f16.f32 "
        "{%0,%1,%2,%3}, {%4,%5,%6,%7}, {%8,%9}, {%0,%1,%2,%3};"
        : "+f"(c[0]), "+f"(c[1]), "+f"(c[2]), "+f"(c[3])
        : "r"(a[0]), "r"(a[1]), "r"(a[2]), "r"(a[3]), "r"(b0), "r"(b1));
}

__global__ __launch_bounds__(256, 2)
void fused_main(const __half* __restrict__ xh,
                const __half* __restrict__ Wxh,
                const __half* __restrict__ Wxl,
                float* __restrict__ out_main) {
    extern __shared__ __align__(16) char smem[];
    const unsigned sb = smem_u32(smem);
    const int tid = threadIdx.x;
    const int wid = tid >> 5, lane = tid & 31;
    const int warp_m = wid & 3;
    const int warp_n = wid >> 2;
    const int bm = blockIdx.y * 128;
    const int bn = blockIdx.x * 128;

    // ---- load A (128 x 256 fp16) once, fully coalesced ----
    {
        const uint4* src = (const uint4*)(xh + (size_t)bm * D_IN);
        #pragma unroll
        for (int t = 0; t < 16; ++t) {
            int slot = t * 256 + tid;            // 4096 uint4 slots
            int row = slot >> 5;                 // 32 uint4 per row
            int c8  = slot & 31;
            *(uint4*)(smem + row * (KSA * 2) + c8 * 16) = src[slot];
        }
    }

    const int brow = tid >> 1;
    const int bcol = (tid & 1) * 16;

    auto load_B = [&](int kc, int stage) {
        char* bh = smem + B_OFF + stage * 2 * B_TILE;
        char* bl = bh + B_TILE;
        const size_t wb = (size_t)(bn + brow) * D_IN + kc + bcol;
        #pragma unroll
        for (int j = 0; j < 2; ++j) {
            unsigned boff = (unsigned)((brow * KSB + bcol + j * 8) * 2);
            *(uint4*)(bh + boff) = *(const uint4*)(Wxh + wb + j * 8);
            *(uint4*)(bl + boff) = *(const uint4*)(Wxl + wb + j * 8);
        }
    };

    float acc[2][8][4];
    #pragma unroll
    for (int m = 0; m < 2; ++m)
        #pragma unroll
        for (int n = 0; n < 8; ++n)
            #pragma unroll
            for (int q = 0; q < 4; ++q) acc[m][n][q] = 0.f;

    auto mma_stage = [&](int kc, int stage) {
        unsigned bbase = sb + B_OFF + stage * 2 * B_TILE;
        #pragma unroll
        for (int ks = 0; ks < 2; ++ks) {
            const int kk = ks * 16 + (lane >> 4) * 8;
            unsigned ah[2][4];
            #pragma unroll
            for (int m = 0; m < 2; ++m) {
                int row = warp_m * 32 + m * 16 + (lane & 15);
                unsigned off = (unsigned)((row * KSA + kc + kk) * 2);
                ldsm_x4(ah[m], sb + off);
            }
            #pragma unroll
            for (int g = 0; g < 4; ++g) {
                int nrow = warp_n * 64 + g * 16 + (lane & 15);
                unsigned off = (unsigned)((nrow * KSB + kk) * 2);
                unsigned bhf[4], blf[4];
                ldsm_x4(bhf, bbase + off);
                ldsm_x4(blf, bbase + B_TILE + off);
                #pragma unroll
                for (int m = 0; m < 2; ++m) {
                    #pragma unroll
                    for (int s = 0; s < 2; ++s) {
                        float* a = acc[m][g * 2 + s];
                        mma_fp16(a, ah[m], bhf[s], bhf[s + 2]);
                        mma_fp16(a, ah[m], blf[s], blf[s + 2]);
                    }
                }
            }
        }
    };

    load_B(0, 0);
    __syncthreads();

    #pragma unroll 1
    for (int c = 0; c < 8; ++c) {
        if (c < 7) load_B((c + 1) * KCH, (c + 1) & 1);
        mma_stage(c * KCH, c & 1);
        __syncthreads();
    }

    // epilogue
    const int gr = lane >> 2;
    const int gc = (lane & 3) * 2;
    #pragma unroll
    for (int m = 0; m < 2; ++m) {
        #pragma unroll
        for (int n = 0; n < 8; ++n) {
            int col = bn + warp_n * 64 + n * 8 + gc;
            float2 bv = *(const float2*)(g_beff + col);
            int r0 = bm + warp_m * 32 + m * 16 + gr;
            float2 o0, o1;
            o0.x = tanh_fast(acc[m][n][0] + bv.x);
            o0.y = tanh_fast(acc[m][n][1] + bv.y);
            o1.x = tanh_fast(acc[m][n][2] + bv.x);
            o1.y = tanh_fast(acc[m][n][3] + bv.y);
            *(float2*)(out_main + (size_t)r0 * D_IN + col)       = o0;
            *(float2*)(out_main + (size_t)(r0 + 8) * D_IN + col) = o1;
        }
    }
}

// ======================= launch ============================================
extern "C" void kernel_launch(void* const* d_in, const int* in_sizes, int n_in,
                              void* d_out, int out_size) {
    const float* x     = (const float*)d_in[0];
    const float* gamma = (const float*)d_in[1];
    const float* beta  = (const float*)d_in[2];
    const float* W1    = (const float*)d_in[3];
    const float* b1    = (const float*)d_in[4];
    const float* W2    = (const float*)d_in[5];
    const float* b2    = (const float*)d_in[6];
    const float* Wf    = (const float*)d_in[7];
    const float* bf    = (const float*)d_in[8];

    float* out_main = (float*)d_out;
    float* out_raw  = (float*)d_out + (size_t)N_ROWS * D_IN;

    float *part0, *T0, *part1;
    __half *Wxh, *Wxl, *xh;
    cudaGetSymbolAddress((void**)&part0, g_part0);
    cudaGetSymbolAddress((void**)&T0,    g_T0);
    cudaGetSymbolAddress((void**)&part1, g_part1);
    cudaGetSymbolAddress((void**)&Wxh,   g_Wxh);
    cudaGetSymbolAddress((void**)&Wxl,   g_Wxl);
    cudaGetSymbolAddress((void**)&xh,    g_xh);

    static cudaStream_t sBN = nullptr, sBias = nullptr, sX = nullptr;
    static cudaEvent_t evFork = nullptr, evBN = nullptr, evBias = nullptr, evX = nullptr;
    static int init_done = 0;
    if (!init_done) {
        cudaFuncSetAttribute(fused_main, cudaFuncAttributeMaxDynamicSharedMemorySize,
                             SMEM_MAIN);
        cudaStreamCreateWithFlags(&sBN,   cudaStreamNonBlocking);
        cudaStreamCreateWithFlags(&sBias, cudaStreamNonBlocking);
        cudaStreamCreateWithFlags(&sX,    cudaStreamNonBlocking);
        cudaEventCreateWithFlags(&evFork, cudaEventDisableTiming);
        cudaEventCreateWithFlags(&evBN,   cudaEventDisableTiming);
        cudaEventCreateWithFlags(&evBias, cudaEventDisableTiming);
        cudaEventCreateWithFlags(&evX,    cudaEventDisableTiming);
        init_done = 1;
    }

    // fork
    cudaEventRecord(evFork, 0);
    cudaStreamWaitEvent(sBN,   evFork, 0);
    cudaStreamWaitEvent(sBias, evFork, 0);
    cudaStreamWaitEvent(sX,    evFork, 0);

    // x -> fp16 branch
    x2half<<<(N_ROWS * D_IN / 8) / 256, 256, 0, sX>>>(x, xh);
    cudaEventRecord(evX, sX);

    // BN branch
    bn_reduce<<<256, 256, 0, sBN>>>(x);
    bn_finalize<<<1, 256, 0, sBN>>>(gamma, beta);
    bn_raw<<<(N_ROWS * D_IN / 4) / 256, 256, 0, sBN>>>(x, out_raw);
    cudaEventRecord(evBN, sBN);

    // bias branch
    bias_chain1<<<F2 / 8, 256, 0, sBias>>>(W2, b1, b2);
    bias_chain2<<<D_IN, 256, 0, sBias>>>(Wf, bf);
    cudaEventRecord(evBias, sBias);

    // weight collapse branch (default stream)
    gemm_nn_split<<<dim3(512 / 64, 256 / 64, 16), 256>>>(Wf, W2, part0, 256, 512, 2048, 128);
    reduce_splits<<<(256 * 512) / 256, 256>>>(part0, T0, 256 * 512, 16);
    gemm_nn_split<<<dim3(256 / 64, 256 / 64, 16), 256>>>(T0, W1, part1, 256, 256, 512, 32);

    // join
    cudaStreamWaitEvent(0, evBN, 0);
    cudaStreamWaitEvent(0, evBias, 0);
    cudaStreamWaitEvent(0, evX, 0);

    fold_bn<<<256, 256>>>();

    fused_main<<<dim3(2, N_ROWS / 128), 256, SMEM_MAIN>>>(xh, Wxh, Wxl, out_main);
}

// round 11
// speedup vs baseline: 32.9253x; 1.1642x over previous
#include <cuda_runtime.h>
#include <cuda_bf16.h>
#include <cuda_fp16.h>
#include <math.h>

#define N_ROWS 65536
#define D_IN   256
#define F1     512
#define F2     2048
#define EPS    1e-5f

// ======================= scratch (device globals) ===========================
__device__ float g_bnpart[2 * 256 * 256];
__device__ __align__(16) float g_scale[D_IN];
__device__ __align__(16) float g_shift[D_IN];
__device__ float g_part0[16 * 256 * 512];
__device__ float g_T0[256 * 512];
__device__ float g_part1[16 * 256 * 256];
__device__ __align__(16) __half g_Wxh[256 * 256];
__device__ __align__(16) __half g_Wxl[256 * 256];
__device__ __align__(16) __half g_xh[(size_t)N_ROWS * D_IN];   // x as fp16 (32 MB)
__device__ float g_v1[F2];
__device__ float g_v2[D_IN];
__device__ __align__(16) float g_beff[D_IN];

__device__ __forceinline__ float tanh_fast(float v) {
    float r;
    asm("tanh.approx.f32 %0, %1;" : "=f"(r) : "f"(v));
    return r;
}

// ============ fused BN reduce + x->fp16 convert (x read ONCE) ==============
__global__ void bn_reduce_conv(const float* __restrict__ x,
                               __half* __restrict__ xh) {
    __shared__ float redS[4][256];
    __shared__ float redQ[4][256];
    const int t = threadIdx.x;
    const int q  = t & 63;       // column quad: cols 4q..4q+3
    const int rg = t >> 6;       // 0..3
    const size_t base_row = (size_t)blockIdx.x * 256;

    float s0 = 0.f, s1 = 0.f, s2 = 0.f, s3 = 0.f;
    float q0 = 0.f, q1 = 0.f, q2 = 0.f, q3 = 0.f;
    #pragma unroll 4
    for (int i = 0; i < 64; ++i) {
        const size_t row = base_row + i * 4 + rg;
        float4 v = *(const float4*)(x + row * D_IN + q * 4);
        s0 += v.x; s1 += v.y; s2 += v.z; s3 += v.w;
        q0 += v.x * v.x; q1 += v.y * v.y; q2 += v.z * v.z; q3 += v.w * v.w;
        __half2 h0 = __floats2half2_rn(v.x, v.y);
        __half2 h1 = __floats2half2_rn(v.z, v.w);
        uint2 pk;
        pk.x = *(unsigned*)&h0; pk.y = *(unsigned*)&h1;
        *(uint2*)(xh + row * D_IN + q * 4) = pk;
    }
    redS[rg][q * 4 + 0] = s0; redS[rg][q * 4 + 1] = s1;
    redS[rg][q * 4 + 2] = s2; redS[rg][q * 4 + 3] = s3;
    redQ[rg][q * 4 + 0] = q0; redQ[rg][q * 4 + 1] = q1;
    redQ[rg][q * 4 + 2] = q2; redQ[rg][q * 4 + 3] = q3;
    __syncthreads();
    if (rg == 0) {
        #pragma unroll
        for (int j = 0; j < 4; ++j) {
            int c = q * 4 + j;
            float s  = redS[0][c] + redS[1][c] + redS[2][c] + redS[3][c];
            float sq = redQ[0][c] + redQ[1][c] + redQ[2][c] + redQ[3][c];
            g_bnpart[blockIdx.x * 256 + c]         = s;
            g_bnpart[65536 + blockIdx.x * 256 + c] = sq;
        }
    }
}

__global__ void bn_finalize(const float* __restrict__ gamma,
                            const float* __restrict__ beta) {
    int j = threadIdx.x;
    float s = 0.f, sq = 0.f;
    #pragma unroll 4
    for (int b = 0; b < 256; ++b) {
        s  += g_bnpart[b * 256 + j];
        sq += g_bnpart[65536 + b * 256 + j];
    }
    float inv_n = 1.0f / (float)N_ROWS;
    float mu  = s * inv_n;
    float var = sq * inv_n - mu * mu;
    float sc  = gamma[j] * rsqrtf(var + EPS);
    g_scale[j] = sc;
    g_shift[j] = beta[j] - mu * sc;
}

// ======================= collapse chain ====================================
__global__ void gemm_nn_split(const float* __restrict__ A,
                              const float* __restrict__ B,
                              float* __restrict__ P,
                              int M, int N, int K, int kchunk) {
    __shared__ float As[16][64];
    __shared__ float Bs[16][65];
    const int tid = threadIdx.x;
    const int tx = tid & 15, ty = tid >> 4;
    const int bn = blockIdx.x * 64, bm = blockIdx.y * 64;
    const int k0 = blockIdx.z * kchunk;

    float acc[4][4];
    #pragma unroll
    for (int i = 0; i < 4; ++i)
        #pragma unroll
        for (int j = 0; j < 4; ++j) acc[i][j] = 0.f;

    for (int kb = k0; kb < k0 + kchunk; kb += 16) {
        #pragma unroll
        for (int t = 0; t < 4; ++t) {
            int idx = tid * 4 + t;
            int r = idx >> 4, kk = idx & 15;
            As[kk][r] = A[(size_t)(bm + r) * K + kb + kk];
        }
        #pragma unroll
        for (int t = 0; t < 4; ++t) {
            int idx = tid + t * 256;
            int c = idx & 63, kk = idx >> 6;
            Bs[kk][c] = B[(size_t)(kb + kk) * N + bn + c];
        }
        __syncthreads();
        #pragma unroll
        for (int kk = 0; kk < 16; ++kk) {
            float a[4], b[4];
            #pragma unroll
            for (int i = 0; i < 4; ++i) a[i] = As[kk][ty * 4 + i];
            #pragma unroll
            for (int j = 0; j < 4; ++j) b[j] = Bs[kk][tx * 4 + j];
            #pragma unroll
            for (int i = 0; i < 4; ++i)
                #pragma unroll
                for (int j = 0; j < 4; ++j)
                    acc[i][j] = fmaf(a[i], b[j], acc[i][j]);
        }
        __syncthreads();
    }
    float* Pb = P + (size_t)blockIdx.z * M * N;
    #pragma unroll
    for (int i = 0; i < 4; ++i)
        #pragma unroll
        for (int j = 0; j < 4; ++j)
            Pb[(size_t)(bm + ty * 4 + i) * N + bn + tx * 4 + j] = acc[i][j];
}

__global__ void reduce_splits(const float* __restrict__ P, float* __restrict__ C,
                              int MN, int S) {
    int i = blockIdx.x * 256 + threadIdx.x;
    if (i >= MN) return;
    float s = 0.f;
    for (int k = 0; k < S; ++k) s += P[(size_t)k * MN + i];
    C[i] = s;
}

__global__ void bias_chain1(const float* __restrict__ W2, const float* __restrict__ b1,
                            const float* __restrict__ b2) {
    int row = blockIdx.x * 8 + (threadIdx.x >> 5);
    int lid = threadIdx.x & 31;
    const float* r = W2 + (size_t)row * F1;
    float s = 0.f;
    #pragma unroll
    for (int k = lid; k < F1; k += 32) s = fmaf(r[k], b1[k], s);
    #pragma unroll
    for (int o = 16; o > 0; o >>= 1) s += __shfl_down_sync(0xFFFFFFFFu, s, o);
    if (lid == 0) g_v1[row] = s + b2[row];
}

__global__ void bias_chain2(const float* __restrict__ Wf, const float* __restrict__ bf) {
    int row = blockIdx.x;
    int t = threadIdx.x;
    const float* r = Wf + (size_t)row * F2;
    float s = 0.f;
    #pragma unroll
    for (int k = t; k < F2; k += 256) s = fmaf(r[k], g_v1[k], s);
    __shared__ float red[256];
    red[t] = s;
    __syncthreads();
    for (int o = 128; o > 0; o >>= 1) {
        if (t < o) red[t] += red[t + o];
        __syncthreads();
    }
    if (t == 0) g_v2[row] = red[0] + bf[row];
}

__global__ void fold_bn() {
    int i = blockIdx.x;
    int t = threadIdx.x;
    float w = 0.f;
    #pragma unroll
    for (int s = 0; s < 16; ++s)
        w += g_part1[s * 65536 + i * D_IN + t];
    float wx = w * g_scale[t];
    __half hi = __float2half_rn(wx);
    float lo = wx - __half2float(hi);
    g_Wxh[i * D_IN + t] = hi;
    g_Wxl[i * D_IN + t] = __float2half_rn(lo);
    __shared__ float red[256];
    red[t] = w * g_shift[t];
    __syncthreads();
    for (int o = 128; o > 0; o >>= 1) {
        if (t < o) red[t] += red[t + o];
        __syncthreads();
    }
    if (t == 0) g_beff[i] = g_v2[i] + red[0];
}

// ======================= fused HMMA main GEMM (fp16 x2) ====================
#define KCH 32
#define KSA 264
#define A_BYTES (128 * KSA * 2)            // 67584
#define KSB 40
#define B_TILE (128 * KSB * 2)             // 10240
#define B_OFF A_BYTES
#define SMEM_MAIN (A_BYTES + 2 * B_TILE)   // 88064 -> 2 CTAs/SM

__device__ __forceinline__ unsigned smem_u32(const void* p) {
    unsigned a;
    asm("{ .reg .u64 t; cvta.to.shared.u64 t, %1; cvt.u32.u64 %0, t; }"
        : "=r"(a) : "l"(p));
    return a;
}

__device__ __forceinline__ void ldsm_x4(unsigned r[4], unsigned addr) {
    asm volatile("ldmatrix.sync.aligned.m8n8.x4.shared.b16 {%0,%1,%2,%3}, [%4];"
                 : "=r"(r[0]), "=r"(r[1]), "=r"(r[2]), "=r"(r[3]) : "r"(addr));
}

__device__ __forceinline__ void mma_fp16(float c[4], const unsigned a[4],
                                         unsigned b0, unsigned b1) {
    asm volatile(
        "mma.sync.aligned.m16n8k16.row.col.f32.f16.f16.f32 "
        "{%0,%1,%2,%3}, {%4,%5,%6,%7}, {%8,%9}, {%0,%1,%2,%3};"
        : "+f"(c[0]), "+f"(c[1]), "+f"(c[2]), "+f"(c[3])
        : "r"(a[0]), "r"(a[1]), "r"(a[2]), "r"(a[3]), "r"(b0), "r"(b1));
}

__global__ __launch_bounds__(256, 2)
void fused_main(const __half* __restrict__ xh,
                const float* __restrict__ x,
                const __half* __restrict__ Wxh,
                const __half* __restrict__ Wxl,
                float* __restrict__ out_main,
                float* __restrict__ raw_out) {
    extern __shared__ __align__(16) char smem[];
    const unsigned sb = smem_u32(smem);
    const int tid = threadIdx.x;
    const int wid = tid >> 5, lane = tid & 31;
    const int warp_m = wid & 3;
    const int warp_n = wid >> 2;
    const int bm = blockIdx.y * 128;
    const int bn = blockIdx.x * 128;

    // ---- load A (128 x 256 fp16) once, coalesced ----
    {
        const uint4* src = (const uint4*)(xh + (size_t)bm * D_IN);
        #pragma unroll
        for (int t = 0; t < 16; ++t) {
            int slot = t * 256 + tid;
            int row = slot >> 5;
            int c8  = slot & 31;
            *(uint4*)(smem + row * (KSA * 2) + c8 * 16) = src[slot];
        }
    }

    const int brow = tid >> 1;
    const int bcol = (tid & 1) * 16;

    uint4 rh[2], rl[2];
    auto load_B_regs = [&](int kc) {
        const size_t wb = (size_t)(bn + brow) * D_IN + kc + bcol;
        rh[0] = *(const uint4*)(Wxh + wb);
        rh[1] = *(const uint4*)(Wxh + wb + 8);
        rl[0] = *(const uint4*)(Wxl + wb);
        rl[1] = *(const uint4*)(Wxl + wb + 8);
    };
    auto sts_B = [&]() {
        char* bh = smem + B_OFF;
        char* bl = bh + B_TILE;
        #pragma unroll
        for (int j = 0; j < 2; ++j) {
            unsigned boff = (unsigned)((brow * KSB + bcol + j * 8) * 2);
            *(uint4*)(bh + boff) = rh[j];
            *(uint4*)(bl + boff) = rl[j];
        }
    };

    float acc[2][8][4];
    #pragma unroll
    for (int m = 0; m < 2; ++m)
        #pragma unroll
        for (int n = 0; n < 8; ++n)
            #pragma unroll
            for (int q = 0; q < 4; ++q) acc[m][n][q] = 0.f;

    auto mma_stage = [&](int kc) {
        unsigned bbase = sb + B_OFF;
        #pragma unroll
        for (int ks = 0; ks < 2; ++ks) {
            const int kk = ks * 16 + (lane >> 4) * 8;
            unsigned ah[2][4];
            #pragma unroll
            for (int m = 0; m < 2; ++m) {
                int row = warp_m * 32 + m * 16 + (lane & 15);
                unsigned off = (unsigned)((row * KSA + kc + kk) * 2);
                ldsm_x4(ah[m], sb + off);
            }
            #pragma unroll
            for (int g = 0; g < 4; ++g) {
                int nrow = warp_n * 64 + g * 16 + (lane & 15);
                unsigned off = (unsigned)((nrow * KSB + kk) * 2);
                unsigned bhf[4], blf[4];
                ldsm_x4(bhf, bbase + off);
                ldsm_x4(blf, bbase + B_TILE + off);
                #pragma unroll
                for (int m = 0; m < 2; ++m) {
                    #pragma unroll
                    for (int s = 0; s < 2; ++s) {
                        float* a = acc[m][g * 2 + s];
                        mma_fp16(a, ah[m], bhf[s], bhf[s + 2]);
                        mma_fp16(a, ah[m], blf[s], blf[s + 2]);
                    }
                }
            }
        }
    };

    load_B_regs(0);
    sts_B();
    __syncthreads();

    #pragma unroll 1
    for (int c = 0; c < 8; ++c) {
        if (c < 7) load_B_regs((c + 1) * KCH);
        mma_stage(c * KCH);
        if (c < 7) {
            __syncthreads();
            sts_B();
            __syncthreads();
        }
    }

    // ---- main epilogue: bias + tanh + store ----
    const int gr = lane >> 2;
    const int gc = (lane & 3) * 2;
    #pragma unroll
    for (int m = 0; m < 2; ++m) {
        #pragma unroll
        for (int n = 0; n < 8; ++n) {
            int col = bn + warp_n * 64 + n * 8 + gc;
            float2 bv = *(const float2*)(g_beff + col);
            int r0 = bm + warp_m * 32 + m * 16 + gr;
            float2 o0, o1;
            o0.x = tanh_fast(acc[m][n][0] + bv.x);
            o0.y = tanh_fast(acc[m][n][1] + bv.y);
            o1.x = tanh_fast(acc[m][n][2] + bv.x);
            o1.y = tanh_fast(acc[m][n][3] + bv.y);
            *(float2*)(out_main + (size_t)r0 * D_IN + col)       = o0;
            *(float2*)(out_main + (size_t)(r0 + 8) * D_IN + col) = o1;
        }
    }

    // ---- raw_feats epilogue (bn==0 CTAs): tanh(x*scale+shift), fp32 x ----
    // 128 rows x 64 float4/row = 8192 positions, 256 threads -> 32 iters.
    if (blockIdx.x == 0) {
        #pragma unroll 8
        for (int j = 0; j < 32; ++j) {
            int pos = j * 256 + tid;
            int row = pos >> 6;                 // 0..127
            int c4  = pos & 63;                 // float4 index within row
            float4 v = *(const float4*)(x + (size_t)(bm + row) * D_IN + c4 * 4);
            float4 sc = *(const float4*)(g_scale + c4 * 4);
            float4 sh = *(const float4*)(g_shift + c4 * 4);
            float4 o;
            o.x = tanh_fast(fmaf(v.x, sc.x, sh.x));
            o.y = tanh_fast(fmaf(v.y, sc.y, sh.y));
            o.z = tanh_fast(fmaf(v.z, sc.z, sh.z));
            o.w = tanh_fast(fmaf(v.w, sc.w, sh.w));
            *(float4*)(raw_out + (size_t)(bm + row) * D_IN + c4 * 4) = o;
        }
    }
}

// ======================= launch ============================================
extern "C" void kernel_launch(void* const* d_in, const int* in_sizes, int n_in,
                              void* d_out, int out_size) {
    const float* x     = (const float*)d_in[0];
    const float* gamma = (const float*)d_in[1];
    const float* beta  = (const float*)d_in[2];
    const float* W1    = (const float*)d_in[3];
    const float* b1    = (const float*)d_in[4];
    const float* W2    = (const float*)d_in[5];
    const float* b2    = (const float*)d_in[6];
    const float* Wf    = (const float*)d_in[7];
    const float* bf    = (const float*)d_in[8];

    float* out_main = (float*)d_out;
    float* out_raw  = (float*)d_out + (size_t)N_ROWS * D_IN;

    float *part0, *T0, *part1;
    __half *Wxh, *Wxl, *xh;
    cudaGetSymbolAddress((void**)&part0, g_part0);
    cudaGetSymbolAddress((void**)&T0,    g_T0);
    cudaGetSymbolAddress((void**)&part1, g_part1);
    cudaGetSymbolAddress((void**)&Wxh,   g_Wxh);
    cudaGetSymbolAddress((void**)&Wxl,   g_Wxl);
    cudaGetSymbolAddress((void**)&xh,    g_xh);

    static cudaStream_t sBN = nullptr, sBias = nullptr;
    static cudaEvent_t evFork = nullptr, evBN = nullptr, evBias = nullptr;
    static int init_done = 0;
    if (!init_done) {
        cudaFuncSetAttribute(fused_main, cudaFuncAttributeMaxDynamicSharedMemorySize,
                             SMEM_MAIN);
        cudaStreamCreateWithFlags(&sBN,   cudaStreamNonBlocking);
        cudaStreamCreateWithFlags(&sBias, cudaStreamNonBlocking);
        cudaEventCreateWithFlags(&evFork, cudaEventDisableTiming);
        cudaEventCreateWithFlags(&evBN,   cudaEventDisableTiming);
        cudaEventCreateWithFlags(&evBias, cudaEventDisableTiming);
        init_done = 1;
    }

    // fork
    cudaEventRecord(evFork, 0);
    cudaStreamWaitEvent(sBN,   evFork, 0);
    cudaStreamWaitEvent(sBias, evFork, 0);

    // BN branch: fused reduce + fp16 convert, then finalize
    bn_reduce_conv<<<256, 256, 0, sBN>>>(x, xh);
    bn_finalize<<<1, 256, 0, sBN>>>(gamma, beta);
    cudaEventRecord(evBN, sBN);

    // bias branch
    bias_chain1<<<F2 / 8, 256, 0, sBias>>>(W2, b1, b2);
    bias_chain2<<<D_IN, 256, 0, sBias>>>(Wf, bf);
    cudaEventRecord(evBias, sBias);

    // weight collapse branch (default stream)
    gemm_nn_split<<<dim3(512 / 64, 256 / 64, 16), 256>>>(Wf, W2, part0, 256, 512, 2048, 128);
    reduce_splits<<<(256 * 512) / 256, 256>>>(part0, T0, 256 * 512, 16);
    gemm_nn_split<<<dim3(256 / 64, 256 / 64, 16), 256>>>(T0, W1, part1, 256, 256, 512, 32);

    // join
    cudaStreamWaitEvent(0, evBN, 0);
    cudaStreamWaitEvent(0, evBias, 0);

    fold_bn<<<256, 256>>>();

    fused_main<<<dim3(2, N_ROWS / 128), 256, SMEM_MAIN>>>(xh, x, Wxh, Wxl,
                                                          out_main, out_raw);
}